// round 10
// baseline (speedup 1.0000x reference)
#include <cuda_runtime.h>
#include <cuda_fp16.h>
#include <math.h>
#include <limits.h>

#define Nn    20000
#define Ee    320000
#define ETOT  340000   // Ee + Nn self loops
#define DIN   128
#define HIDC  128
#define NH1   4
#define F1    512      // NH1*HIDC
#define DOUT  32
#define NTILES ((Nn + 255) / 256)   // 79

// ---------------- scratch (device globals; allocation-free) ----------------
__device__ __align__(16) float  g_h0  [Nn*DIN];
__device__ __align__(16) __half g_xh1 [(size_t)Nn*F1];
__device__ __align__(16) float  g_al1s[Nn*NH1];
__device__ __align__(16) float  g_al1d[Nn*NH1];
__device__ __align__(16) float  g_h1  [(size_t)Nn*F1];
__device__ __align__(16) __half g_xh2 [Nn*HIDC];
__device__              float   g_al2s[Nn];
__device__              float   g_al2d[Nn];
__device__ __align__(16) float  g_h2  [Nn*HIDC];
__device__              int     g_src [ETOT];
__device__              int     g_dst [ETOT];
__device__              int     g_deg [Nn];
__device__              int     g_scantmp[Nn];
__device__              int     g_tilesum[128];
__device__              int     g_tileoff[128];
__device__              int     g_rowptr[Nn+1];
__device__              int     g_cursor[Nn];
__device__              int     g_csr_src[ETOT];
__device__              int     g_is32;

// ---------------- helpers ----------------
__device__ __forceinline__ float wsum(float v){
    #pragma unroll
    for (int o = 16; o; o >>= 1) v += __shfl_xor_sync(0xffffffffu, v, o);
    return v;
}
__device__ __forceinline__ float wmax(float v){
    #pragma unroll
    for (int o = 16; o; o >>= 1) v = fmaxf(v, __shfl_xor_sync(0xffffffffu, v, o));
    return v;
}
__device__ __forceinline__ float gelu_exact(float x){
    return 0.5f * x * (1.0f + erff(x * 0.70710678118654752f));
}
__device__ __forceinline__ unsigned tf32_of(float x){
    unsigned u; asm("cvt.rna.tf32.f32 %0, %1;" : "=r"(u) : "f"(x)); return u;
}
__device__ __forceinline__ float lrelu(float x){ return x > 0.f ? x : 0.2f * x; }

__device__ __forceinline__ float4 h4_to_f4(uint2 u){
    __half2 lo = *reinterpret_cast<__half2*>(&u.x);
    __half2 hi = *reinterpret_cast<__half2*>(&u.y);
    float2 a = __half22float2(lo), b = __half22float2(hi);
    return make_float4(a.x, a.y, b.x, b.y);
}

// ---------------- edge dtype detection + decode (+degree count) ----------------
__global__ void detect_dtype(const long long* __restrict__ p){
    long long stride = (2LL * Ee) / 4096;
    if (stride < 1) stride = 1;
    long long idx = (long long)(blockIdx.x * blockDim.x + threadIdx.x) * stride;
    if (idx >= 2LL * Ee) return;
    long long v = p[idx];
    if (v < 0 || v >= Nn) atomicExch(&g_is32, 1);
}

__global__ void decode_edges(const int* __restrict__ p32){
    int e = blockIdx.x * blockDim.x + threadIdx.x;
    if (e >= ETOT) return;
    int s, d;
    if (e < Ee){
        if (g_is32){ s = p32[e];   d = p32[Ee + e]; }
        else       { s = p32[2*e]; d = p32[2*Ee + 2*e]; }
    } else {
        s = d = e - Ee;
    }
    g_src[e] = s; g_dst[e] = d;
    atomicAdd(&g_deg[d], 1);
}

// ---------------- parallel 3-kernel scan of g_deg -> g_rowptr ----------------
__global__ void scan_tiles(){
    __shared__ int sh[256];
    int i = blockIdx.x * 256 + threadIdx.x;
    int v = (i < Nn) ? g_deg[i] : 0;
    sh[threadIdx.x] = v;
    __syncthreads();
    for (int off = 1; off < 256; off <<= 1){
        int t = (threadIdx.x >= off) ? sh[threadIdx.x - off] : 0;
        __syncthreads();
        sh[threadIdx.x] += t;
        __syncthreads();
    }
    if (i < Nn) g_scantmp[i] = sh[threadIdx.x];
    if (threadIdx.x == 255) g_tilesum[blockIdx.x] = sh[255];
}

__global__ void scan_sums(){
    __shared__ int sh[128];
    int t = threadIdx.x;
    sh[t] = (t < NTILES) ? g_tilesum[t] : 0;
    __syncthreads();
    for (int off = 1; off < 128; off <<= 1){
        int v = (t >= off) ? sh[t - off] : 0;
        __syncthreads();
        sh[t] += v;
        __syncthreads();
    }
    if (t < NTILES) g_tileoff[t] = (t == 0) ? 0 : sh[t - 1];
}

__global__ void scan_finalize(){
    int i = blockIdx.x * 256 + threadIdx.x;
    if (i >= Nn) return;
    int r = g_scantmp[i] - g_deg[i] + g_tileoff[i >> 8];
    g_rowptr[i] = r;
    g_cursor[i] = r;
    if (i == 0) g_rowptr[Nn] = ETOT;
}

__global__ void build_csr(){
    int e = blockIdx.x * blockDim.x + threadIdx.x;
    if (e >= ETOT) return;
    int pos = atomicAdd(&g_cursor[g_dst[e]], 1);
    g_csr_src[pos] = g_src[e];
}

// ---------------- standalone LayerNorm (input only) ----------------
template<int D>
__global__ void ln_kernel(const float* __restrict__ in, const float* __restrict__ g,
                          const float* __restrict__ b, float* __restrict__ out){
    int row = blockIdx.x * (blockDim.x >> 5) + (threadIdx.x >> 5);
    if (row >= Nn) return;
    int lane = threadIdx.x & 31;
    constexpr int V = D / 128;
    float4 v[V];
    const float4* ir = (const float4*)(in + (size_t)row * D);
    float s = 0.f;
    #pragma unroll
    for (int i = 0; i < V; i++){
        v[i] = ir[lane + i*32];
        s += v[i].x + v[i].y + v[i].z + v[i].w;
    }
    s = wsum(s);
    float mu = s * (1.0f / D);
    float q = 0.f;
    #pragma unroll
    for (int i = 0; i < V; i++){
        float dx;
        dx = v[i].x - mu; q += dx*dx;
        dx = v[i].y - mu; q += dx*dx;
        dx = v[i].z - mu; q += dx*dx;
        dx = v[i].w - mu; q += dx*dx;
    }
    q = wsum(q);
    float rstd = rsqrtf(q * (1.0f / D) + 1e-5f);
    float4* orow = (float4*)(out + (size_t)row * D);
    #pragma unroll
    for (int i = 0; i < V; i++){
        float4 gg = ((const float4*)g)[lane + i*32];
        float4 bb = ((const float4*)b)[lane + i*32];
        float4 y;
        y.x = (v[i].x - mu) * rstd * gg.x + bb.x;
        y.y = (v[i].y - mu) * rstd * gg.y + bb.y;
        y.z = (v[i].z - mu) * rstd * gg.z + bb.z;
        y.w = (v[i].w - mu) * rstd * gg.w + bb.w;
        orow[lane + i*32] = y;
    }
}

// ------- tf32 GEMM, fp16 output, fused attn-logit partials via atomics -------
// C[n,m](fp16) = A[n,k] @ B[k,m]; als/ald[r*H + h] += dot(C_row_slice, att)
#define GBM 128
#define GBN 64
#define GBK 32
#define AS_STRIDE (GBK + 4)
#define BS_STRIDE (GBN + 4)

template<int H>
__global__ void __launch_bounds__(256, 2) gemm_tf32_fused(const float* __restrict__ A,
                                                          const float* __restrict__ B,
                                                          __half* __restrict__ C,
                                                          int n, int k, int m,
                                                          const float* __restrict__ att_s,
                                                          const float* __restrict__ att_d,
                                                          float* __restrict__ als,
                                                          float* __restrict__ ald){
    __shared__ float As[GBM][AS_STRIDE];
    __shared__ float Bs[GBK][BS_STRIDE];
    __shared__ float satt_s[GBN], satt_d[GBN];

    int tid  = threadIdx.x;
    int wid  = tid >> 5;
    int lane = tid & 31;
    int wm   = (wid & 3) * 32;
    int wn   = (wid >> 2) * 32;
    int grp  = lane >> 2;
    int tg   = lane & 3;

    int bm = blockIdx.y * GBM;
    int bn = blockIdx.x * GBN;

    if (tid < GBN)                    satt_s[tid] = att_s[bn + tid];
    else if (tid < 2*GBN)             satt_d[tid - GBN] = att_d[bn + tid - GBN];

    float acc[2][4][4];
    #pragma unroll
    for (int i=0;i<2;i++)
        #pragma unroll
        for (int j=0;j<4;j++)
            #pragma unroll
            for (int l=0;l<4;l++) acc[i][j][l] = 0.f;

    int arow  = tid >> 3;
    int acol  = (tid & 7) * 4;
    int brow  = tid >> 4;
    int bcol  = (tid & 15) * 4;

    for (int k0 = 0; k0 < k; k0 += GBK){
        #pragma unroll
        for (int i = 0; i < 4; i++){
            int row = arow + i*32;
            float4 v = make_float4(0,0,0,0);
            int gr = bm + row;
            if (gr < n) v = *(const float4*)&A[(size_t)gr * k + k0 + acol];
            As[row][acol+0] = __uint_as_float(tf32_of(v.x));
            As[row][acol+1] = __uint_as_float(tf32_of(v.y));
            As[row][acol+2] = __uint_as_float(tf32_of(v.z));
            As[row][acol+3] = __uint_as_float(tf32_of(v.w));
        }
        #pragma unroll
        for (int i = 0; i < 2; i++){
            int row = brow + i*16;
            float4 v = *(const float4*)&B[(size_t)(k0 + row) * m + bn + bcol];
            Bs[row][bcol+0] = __uint_as_float(tf32_of(v.x));
            Bs[row][bcol+1] = __uint_as_float(tf32_of(v.y));
            Bs[row][bcol+2] = __uint_as_float(tf32_of(v.z));
            Bs[row][bcol+3] = __uint_as_float(tf32_of(v.w));
        }
        __syncthreads();

        #pragma unroll
        for (int kk = 0; kk < 4; kk++){
            unsigned a[2][4], bfr[4][2];
            #pragma unroll
            for (int mt = 0; mt < 2; mt++){
                int r = wm + mt*16 + grp;
                int c = kk*8 + tg;
                a[mt][0] = __float_as_uint(As[r    ][c    ]);
                a[mt][1] = __float_as_uint(As[r + 8][c    ]);
                a[mt][2] = __float_as_uint(As[r    ][c + 4]);
                a[mt][3] = __float_as_uint(As[r + 8][c + 4]);
            }
            #pragma unroll
            for (int nt = 0; nt < 4; nt++){
                int c = wn + nt*8 + grp;
                int r = kk*8 + tg;
                bfr[nt][0] = __float_as_uint(Bs[r    ][c]);
                bfr[nt][1] = __float_as_uint(Bs[r + 4][c]);
            }
            #pragma unroll
            for (int mt = 0; mt < 2; mt++)
                #pragma unroll
                for (int nt = 0; nt < 4; nt++){
                    asm volatile(
                        "mma.sync.aligned.m16n8k8.row.col.f32.tf32.tf32.f32 "
                        "{%0,%1,%2,%3}, {%4,%5,%6,%7}, {%8,%9}, {%0,%1,%2,%3};"
                        : "+f"(acc[mt][nt][0]), "+f"(acc[mt][nt][1]),
                          "+f"(acc[mt][nt][2]), "+f"(acc[mt][nt][3])
                        : "r"(a[mt][0]), "r"(a[mt][1]), "r"(a[mt][2]), "r"(a[mt][3]),
                          "r"(bfr[nt][0]), "r"(bfr[nt][1]));
                }
        }
        __syncthreads();
    }

    // epilogue: fp16 store + attn-logit partial dots
    int h = (bn + wn) >> 7;   // head index (128 cols per head)
    #pragma unroll
    for (int mt = 0; mt < 2; mt++){
        int r0 = bm + wm + mt*16 + grp;
        int r1 = r0 + 8;
        float ps0=0.f, pd0=0.f, ps1=0.f, pd1=0.f;
        #pragma unroll
        for (int nt = 0; nt < 4; nt++){
            int cl = wn + nt*8 + 2*tg;
            float as0 = satt_s[cl], as1 = satt_s[cl+1];
            float ad0 = satt_d[cl], ad1 = satt_d[cl+1];
            ps0 += acc[mt][nt][0]*as0 + acc[mt][nt][1]*as1;
            pd0 += acc[mt][nt][0]*ad0 + acc[mt][nt][1]*ad1;
            ps1 += acc[mt][nt][2]*as0 + acc[mt][nt][3]*as1;
            pd1 += acc[mt][nt][2]*ad0 + acc[mt][nt][3]*ad1;
            int c = bn + cl;
            if (r0 < n) *(__half2*)&C[(size_t)r0 * m + c] = __floats2half2_rn(acc[mt][nt][0], acc[mt][nt][1]);
            if (r1 < n) *(__half2*)&C[(size_t)r1 * m + c] = __floats2half2_rn(acc[mt][nt][2], acc[mt][nt][3]);
        }
        // reduce across the 4 tg lanes of each quad
        ps0 += __shfl_xor_sync(0xffffffffu, ps0, 1); ps0 += __shfl_xor_sync(0xffffffffu, ps0, 2);
        pd0 += __shfl_xor_sync(0xffffffffu, pd0, 1); pd0 += __shfl_xor_sync(0xffffffffu, pd0, 2);
        ps1 += __shfl_xor_sync(0xffffffffu, ps1, 1); ps1 += __shfl_xor_sync(0xffffffffu, ps1, 2);
        pd1 += __shfl_xor_sync(0xffffffffu, pd1, 1); pd1 += __shfl_xor_sync(0xffffffffu, pd1, 2);
        if (tg == 0){
            if (r0 < n){ atomicAdd(&als[r0*H + h], ps0); atomicAdd(&ald[r0*H + h], pd0); }
            if (r1 < n){ atomicAdd(&als[r1*H + h], ps1); atomicAdd(&ald[r1*H + h], pd1); }
        }
    }
}

// ---------------- GAT agg H=4 (fp16 features) + bias + LN + GELU -> h1 ----------------
__global__ void __launch_bounds__(256) gat_agg4_fused(const float4* __restrict__ als4,
                                                      const float4* __restrict__ ald4,
                                                      const __half* __restrict__ xh,
                                                      const float* __restrict__ bias,
                                                      const float* __restrict__ gw,
                                                      const float* __restrict__ bw,
                                                      float* __restrict__ h1){
    int node = blockIdx.x * (blockDim.x >> 5) + (threadIdx.x >> 5);
    if (node >= Nn) return;
    int lane = threadIdx.x & 31;
    float4 ad = ald4[node];
    int pbeg = g_rowptr[node], pend = g_rowptr[node+1];

    // phase A: per-head max
    float m0=-1e30f, m1=-1e30f, m2=-1e30f, m3=-1e30f;
    for (int p = pbeg + lane; p < pend; p += 32){
        float4 as = als4[g_csr_src[p]];
        m0 = fmaxf(m0, lrelu(as.x + ad.x));
        m1 = fmaxf(m1, lrelu(as.y + ad.y));
        m2 = fmaxf(m2, lrelu(as.z + ad.z));
        m3 = fmaxf(m3, lrelu(as.w + ad.w));
    }
    m0 = wmax(m0); m1 = wmax(m1); m2 = wmax(m2); m3 = wmax(m3);

    // phase B: denominators
    float d0=0.f, d1=0.f, d2=0.f, d3=0.f;
    for (int p = pbeg + lane; p < pend; p += 32){
        float4 as = als4[g_csr_src[p]];
        d0 += __expf(lrelu(as.x + ad.x) - m0);
        d1 += __expf(lrelu(as.y + ad.y) - m1);
        d2 += __expf(lrelu(as.z + ad.z) - m2);
        d3 += __expf(lrelu(as.w + ad.w) - m3);
    }
    d0 = wsum(d0); d1 = wsum(d1); d2 = wsum(d2); d3 = wsum(d3);
    float r0 = 1.f/d0, r1 = 1.f/d1, r2 = 1.f/d2, r3 = 1.f/d3;

    // phase C: independent fp16 feature accumulation
    float4 a0 = make_float4(0,0,0,0), a1 = a0, a2 = a0, a3 = a0;
    #pragma unroll 2
    for (int p = pbeg; p < pend; p++){
        int s = g_csr_src[p];
        float4 as = als4[s];
        const uint2* xr = (const uint2*)(xh + (size_t)s * F1);
        float4 x0 = h4_to_f4(xr[lane]);
        float4 x1 = h4_to_f4(xr[32 + lane]);
        float4 x2 = h4_to_f4(xr[64 + lane]);
        float4 x3 = h4_to_f4(xr[96 + lane]);
        float e0 = __expf(lrelu(as.x + ad.x) - m0);
        float e1 = __expf(lrelu(as.y + ad.y) - m1);
        float e2 = __expf(lrelu(as.z + ad.z) - m2);
        float e3 = __expf(lrelu(as.w + ad.w) - m3);
        a0.x += e0*x0.x; a0.y += e0*x0.y; a0.z += e0*x0.z; a0.w += e0*x0.w;
        a1.x += e1*x1.x; a1.y += e1*x1.y; a1.z += e1*x1.z; a1.w += e1*x1.w;
        a2.x += e2*x2.x; a2.y += e2*x2.y; a2.z += e2*x2.z; a2.w += e2*x2.w;
        a3.x += e3*x3.x; a3.y += e3*x3.y; a3.z += e3*x3.z; a3.w += e3*x3.w;
    }

    // epilogue: bias + LN(512) + GELU
    const float4* b4 = (const float4*)bias;
    float4 q0 = b4[lane], q1 = b4[32+lane], q2 = b4[64+lane], q3 = b4[96+lane];
    float4 v0, v1, v2, v3;
    v0.x = a0.x*r0 + q0.x; v0.y = a0.y*r0 + q0.y; v0.z = a0.z*r0 + q0.z; v0.w = a0.w*r0 + q0.w;
    v1.x = a1.x*r1 + q1.x; v1.y = a1.y*r1 + q1.y; v1.z = a1.z*r1 + q1.z; v1.w = a1.w*r1 + q1.w;
    v2.x = a2.x*r2 + q2.x; v2.y = a2.y*r2 + q2.y; v2.z = a2.z*r2 + q2.z; v2.w = a2.w*r2 + q2.w;
    v3.x = a3.x*r3 + q3.x; v3.y = a3.y*r3 + q3.y; v3.z = a3.z*r3 + q3.z; v3.w = a3.w*r3 + q3.w;

    float s = v0.x+v0.y+v0.z+v0.w + v1.x+v1.y+v1.z+v1.w
            + v2.x+v2.y+v2.z+v2.w + v3.x+v3.y+v3.z+v3.w;
    s = wsum(s);
    float mu = s * (1.0f / F1);
    float q = 0.f, dx;
    dx=v0.x-mu; q+=dx*dx; dx=v0.y-mu; q+=dx*dx; dx=v0.z-mu; q+=dx*dx; dx=v0.w-mu; q+=dx*dx;
    dx=v1.x-mu; q+=dx*dx; dx=v1.y-mu; q+=dx*dx; dx=v1.z-mu; q+=dx*dx; dx=v1.w-mu; q+=dx*dx;
    dx=v2.x-mu; q+=dx*dx; dx=v2.y-mu; q+=dx*dx; dx=v2.z-mu; q+=dx*dx; dx=v2.w-mu; q+=dx*dx;
    dx=v3.x-mu; q+=dx*dx; dx=v3.y-mu; q+=dx*dx; dx=v3.z-mu; q+=dx*dx; dx=v3.w-mu; q+=dx*dx;
    q = wsum(q);
    float rstd = rsqrtf(q * (1.0f / F1) + 1e-5f);

    const float4* g4 = (const float4*)gw;
    const float4* w4 = (const float4*)bw;
    float4* orow = (float4*)(h1 + (size_t)node * F1);
    float4 vv[4] = {v0, v1, v2, v3};
    #pragma unroll
    for (int i = 0; i < 4; i++){
        float4 gg = g4[i*32 + lane];
        float4 bb = w4[i*32 + lane];
        float4 y;
        y.x = gelu_exact((vv[i].x - mu) * rstd * gg.x + bb.x);
        y.y = gelu_exact((vv[i].y - mu) * rstd * gg.y + bb.y);
        y.z = gelu_exact((vv[i].z - mu) * rstd * gg.z + bb.z);
        y.w = gelu_exact((vv[i].w - mu) * rstd * gg.w + bb.w);
        orow[i*32 + lane] = y;
    }
}

// ---------------- GAT agg H=1 (fp16 features) + bias + LN + GELU -> h2 ----------------
__global__ void __launch_bounds__(256) gat_agg1_fused(const float* __restrict__ als,
                                                      const float* __restrict__ ald,
                                                      const __half* __restrict__ xh,
                                                      const float* __restrict__ bias,
                                                      const float* __restrict__ gw,
                                                      const float* __restrict__ bw,
                                                      float* __restrict__ h2){
    int node = blockIdx.x * (blockDim.x >> 5) + (threadIdx.x >> 5);
    if (node >= Nn) return;
    int lane = threadIdx.x & 31;
    float ad = ald[node];
    int pbeg = g_rowptr[node], pend = g_rowptr[node+1];

    float m = -1e30f;
    for (int p = pbeg + lane; p < pend; p += 32)
        m = fmaxf(m, lrelu(als[g_csr_src[p]] + ad));
    m = wmax(m);

    float den = 0.f;
    for (int p = pbeg + lane; p < pend; p += 32)
        den += __expf(lrelu(als[g_csr_src[p]] + ad) - m);
    den = wsum(den);
    float r = 1.f/den;

    float4 acc = make_float4(0,0,0,0);
    #pragma unroll 2
    for (int p = pbeg; p < pend; p++){
        int s = g_csr_src[p];
        float e = __expf(lrelu(als[s] + ad) - m);
        float4 xv = h4_to_f4(((const uint2*)(xh + (size_t)s * HIDC))[lane]);
        acc.x += e*xv.x; acc.y += e*xv.y; acc.z += e*xv.z; acc.w += e*xv.w;
    }

    float4 qb = ((const float4*)bias)[lane];
    float4 v;
    v.x = acc.x*r + qb.x; v.y = acc.y*r + qb.y; v.z = acc.z*r + qb.z; v.w = acc.w*r + qb.w;
    float s = wsum(v.x + v.y + v.z + v.w);
    float mu = s * (1.0f / HIDC);
    float q = 0.f, dx;
    dx=v.x-mu; q+=dx*dx; dx=v.y-mu; q+=dx*dx; dx=v.z-mu; q+=dx*dx; dx=v.w-mu; q+=dx*dx;
    q = wsum(q);
    float rstd = rsqrtf(q * (1.0f / HIDC) + 1e-5f);
    float4 gg = ((const float4*)gw)[lane];
    float4 bb = ((const float4*)bw)[lane];
    float4 y;
    y.x = gelu_exact((v.x - mu) * rstd * gg.x + bb.x);
    y.y = gelu_exact((v.y - mu) * rstd * gg.y + bb.y);
    y.z = gelu_exact((v.z - mu) * rstd * gg.z + bb.z);
    y.w = gelu_exact((v.w - mu) * rstd * gg.w + bb.w);
    ((float4*)(h2 + (size_t)node * HIDC))[lane] = y;
}

// ---------------- fused output projection + log_softmax ----------------
__global__ void out_proj(const float* __restrict__ h2, const float* __restrict__ Wo,
                         const float* __restrict__ bo, float* __restrict__ out){
    int w = (blockIdx.x * blockDim.x + threadIdx.x) >> 5;
    if (w >= Nn) return;
    int lane = threadIdx.x & 31;
    const float* hr = h2 + (size_t)w * HIDC;
    float acc = bo[lane];
    #pragma unroll 8
    for (int k = 0; k < HIDC; k++)
        acc += hr[k] * Wo[k * DOUT + lane];
    float mx = wmax(acc);
    float ex = expf(acc - mx);
    float sm = wsum(ex);
    out[(size_t)w * DOUT + lane] = acc - mx - logf(sm);
}

// ---------------- launch ----------------
extern "C" void kernel_launch(void* const* d_in, const int* in_sizes, int n_in,
                              void* d_out, int out_size){
    const float* x      = (const float*)d_in[0];
    const void*  ei     = d_in[1];
    const float* g_in   = (const float*)d_in[2];
    const float* b_in   = (const float*)d_in[3];
    const float* W1     = (const float*)d_in[4];
    const float* att1_s = (const float*)d_in[5];
    const float* att1_d = (const float*)d_in[6];
    const float* bias1  = (const float*)d_in[7];
    const float* g1     = (const float*)d_in[8];
    const float* b1     = (const float*)d_in[9];
    const float* W2     = (const float*)d_in[10];
    const float* att2_s = (const float*)d_in[11];
    const float* att2_d = (const float*)d_in[12];
    const float* bias2  = (const float*)d_in[13];
    const float* g2     = (const float*)d_in[14];
    const float* b2     = (const float*)d_in[15];
    const float* Wo     = (const float*)d_in[16];
    const float* bo     = (const float*)d_in[17];
    float* out = (float*)d_out;

    void *p_h0, *p_xh1, *p_al1s, *p_al1d, *p_h1;
    void *p_xh2, *p_al2s, *p_al2d, *p_h2, *p_is32, *p_deg;
    cudaGetSymbolAddress(&p_h0,   g_h0);
    cudaGetSymbolAddress(&p_xh1,  g_xh1);
    cudaGetSymbolAddress(&p_al1s, g_al1s);
    cudaGetSymbolAddress(&p_al1d, g_al1d);
    cudaGetSymbolAddress(&p_h1,   g_h1);
    cudaGetSymbolAddress(&p_xh2,  g_xh2);
    cudaGetSymbolAddress(&p_al2s, g_al2s);
    cudaGetSymbolAddress(&p_al2d, g_al2d);
    cudaGetSymbolAddress(&p_h2,   g_h2);
    cudaGetSymbolAddress(&p_is32, g_is32);
    cudaGetSymbolAddress(&p_deg,  g_deg);

    const int T = 256;
    const int warpsPB = T / 32;

    // ---- side stream for CSR build ----
    cudaStream_t s2;
    cudaStreamCreate(&s2);
    cudaEvent_t evF, evJ;
    cudaEventCreateWithFlags(&evF, cudaEventDisableTiming);
    cudaEventCreateWithFlags(&evJ, cudaEventDisableTiming);

    cudaEventRecord(evF, 0);
    cudaStreamWaitEvent(s2, evF, 0);

    cudaMemsetAsync(p_is32, 0, sizeof(int), s2);
    cudaMemsetAsync(p_deg,  0, Nn * sizeof(int), s2);
    detect_dtype<<<16, 256, 0, s2>>>((const long long*)ei);
    decode_edges<<<(ETOT + T - 1)/T, T, 0, s2>>>((const int*)ei);
    scan_tiles<<<NTILES, 256, 0, s2>>>();
    scan_sums<<<1, 128, 0, s2>>>();
    scan_finalize<<<NTILES, 256, 0, s2>>>();
    build_csr<<<(ETOT + T - 1)/T, T, 0, s2>>>();
    cudaEventRecord(evJ, s2);

    // ---- dense path on main stream ----
    cudaMemsetAsync(p_al1s, 0, Nn * NH1 * sizeof(float));
    cudaMemsetAsync(p_al1d, 0, Nn * NH1 * sizeof(float));
    cudaMemsetAsync(p_al2s, 0, Nn * sizeof(float));
    cudaMemsetAsync(p_al2d, 0, Nn * sizeof(float));

    ln_kernel<128><<<(Nn + warpsPB - 1)/warpsPB, T>>>(x, g_in, b_in, (float*)p_h0);
    {
        dim3 grid(F1/GBN, (Nn + GBM - 1)/GBM);
        gemm_tf32_fused<NH1><<<grid, 256>>>((const float*)p_h0, W1, (__half*)p_xh1,
                                            Nn, DIN, F1, att1_s, att1_d,
                                            (float*)p_al1s, (float*)p_al1d);
    }

    // join CSR before aggregation
    cudaStreamWaitEvent(0, evJ, 0);

    gat_agg4_fused<<<(Nn + warpsPB - 1)/warpsPB, T>>>((const float4*)p_al1s, (const float4*)p_al1d,
                                                      (const __half*)p_xh1, bias1, g1, b1,
                                                      (float*)p_h1);

    {
        dim3 grid(HIDC/GBN, (Nn + GBM - 1)/GBM);
        gemm_tf32_fused<1><<<grid, 256>>>((const float*)p_h1, W2, (__half*)p_xh2,
                                          Nn, F1, HIDC, att2_s, att2_d,
                                          (float*)p_al2s, (float*)p_al2d);
    }
    gat_agg1_fused<<<(Nn + warpsPB - 1)/warpsPB, T>>>((const float*)p_al2s, (const float*)p_al2d,
                                                      (const __half*)p_xh2, bias2, g2, b2,
                                                      (float*)p_h2);

    out_proj<<<(Nn + warpsPB - 1)/warpsPB, T>>>((const float*)p_h2, Wo, bo, out);
}

// round 11
// speedup vs baseline: 1.4263x; 1.4263x over previous
#include <cuda_runtime.h>
#include <cuda_bf16.h>
#include <math.h>
#include <limits.h>

#define Nn    20000
#define Ee    320000
#define ETOT  340000   // Ee + Nn self loops
#define DIN   128
#define HIDC  128
#define NH1   4
#define F1    512      // NH1*HIDC
#define DOUT  32
#define NTILES ((Nn + 255) / 256)   // 79

// ---------------- scratch (device globals; allocation-free) ----------------
__device__ __align__(16) float g_h0  [Nn*DIN];
__device__ __align__(16) float g_xh1 [(size_t)Nn*F1];
__device__ __align__(16) float g_al1s[Nn*NH1];
__device__ __align__(16) float g_al1d[Nn*NH1];
__device__ __align__(16) float g_h1  [(size_t)Nn*F1];
__device__ __align__(16) float g_xh2 [Nn*HIDC];
__device__             float  g_al2s[Nn];
__device__             float  g_al2d[Nn];
__device__             int    g_src [ETOT];
__device__             int    g_dst [ETOT];
__device__             int    g_deg [Nn];
__device__             int    g_scantmp[Nn];
__device__             int    g_tilesum[128];
__device__             int    g_tileoff[128];
__device__             int    g_rowptr[Nn+1];
__device__             int    g_cursor[Nn];
__device__             int    g_csr_src[ETOT];
__device__             int    g_is32;

// ---------------- helpers ----------------
__device__ __forceinline__ float wsum(float v){
    #pragma unroll
    for (int o = 16; o; o >>= 1) v += __shfl_xor_sync(0xffffffffu, v, o);
    return v;
}
__device__ __forceinline__ float wmax(float v){
    #pragma unroll
    for (int o = 16; o; o >>= 1) v = fmaxf(v, __shfl_xor_sync(0xffffffffu, v, o));
    return v;
}
__device__ __forceinline__ float gelu_exact(float x){
    return 0.5f * x * (1.0f + erff(x * 0.70710678118654752f));
}
__device__ __forceinline__ unsigned tf32_of(float x){
    unsigned u; asm("cvt.rna.tf32.f32 %0, %1;" : "=r"(u) : "f"(x)); return u;
}
__device__ __forceinline__ float lrelu(float x){ return x > 0.f ? x : 0.2f * x; }

// ---------------- edge dtype detection + decode (+degree count) ----------------
__global__ void detect_dtype(const long long* __restrict__ p){
    long long stride = (2LL * Ee) / 4096;
    if (stride < 1) stride = 1;
    long long idx = (long long)(blockIdx.x * blockDim.x + threadIdx.x) * stride;
    if (idx >= 2LL * Ee) return;
    long long v = p[idx];
    if (v < 0 || v >= Nn) atomicExch(&g_is32, 1);
}

__global__ void decode_edges(const int* __restrict__ p32){
    int e = blockIdx.x * blockDim.x + threadIdx.x;
    if (e >= ETOT) return;
    int s, d;
    if (e < Ee){
        if (g_is32){ s = p32[e];   d = p32[Ee + e]; }
        else       { s = p32[2*e]; d = p32[2*Ee + 2*e]; }
    } else {
        s = d = e - Ee;
    }
    g_src[e] = s; g_dst[e] = d;
    atomicAdd(&g_deg[d], 1);
}

// ---------------- parallel 3-kernel scan of g_deg -> g_rowptr ----------------
__global__ void scan_tiles(){
    __shared__ int sh[256];
    int i = blockIdx.x * 256 + threadIdx.x;
    int v = (i < Nn) ? g_deg[i] : 0;
    sh[threadIdx.x] = v;
    __syncthreads();
    for (int off = 1; off < 256; off <<= 1){
        int t = (threadIdx.x >= off) ? sh[threadIdx.x - off] : 0;
        __syncthreads();
        sh[threadIdx.x] += t;
        __syncthreads();
    }
    if (i < Nn) g_scantmp[i] = sh[threadIdx.x];
    if (threadIdx.x == 255) g_tilesum[blockIdx.x] = sh[255];
}

__global__ void scan_sums(){
    __shared__ int sh[128];
    int t = threadIdx.x;
    sh[t] = (t < NTILES) ? g_tilesum[t] : 0;
    __syncthreads();
    for (int off = 1; off < 128; off <<= 1){
        int v = (t >= off) ? sh[t - off] : 0;
        __syncthreads();
        sh[t] += v;
        __syncthreads();
    }
    if (t < NTILES) g_tileoff[t] = (t == 0) ? 0 : sh[t - 1];
}

__global__ void scan_finalize(){
    int i = blockIdx.x * 256 + threadIdx.x;
    if (i >= Nn) return;
    int r = g_scantmp[i] - g_deg[i] + g_tileoff[i >> 8];
    g_rowptr[i] = r;
    g_cursor[i] = r;
    if (i == 0) g_rowptr[Nn] = ETOT;
}

__global__ void build_csr(){
    int e = blockIdx.x * blockDim.x + threadIdx.x;
    if (e >= ETOT) return;
    int pos = atomicAdd(&g_cursor[g_dst[e]], 1);
    g_csr_src[pos] = g_src[e];
}

// ---------------- standalone LayerNorm (input only) ----------------
template<int D>
__global__ void ln_kernel(const float* __restrict__ in, const float* __restrict__ g,
                          const float* __restrict__ b, float* __restrict__ out){
    int row = blockIdx.x * (blockDim.x >> 5) + (threadIdx.x >> 5);
    if (row >= Nn) return;
    int lane = threadIdx.x & 31;
    constexpr int V = D / 128;
    float4 v[V];
    const float4* ir = (const float4*)(in + (size_t)row * D);
    float s = 0.f;
    #pragma unroll
    for (int i = 0; i < V; i++){
        v[i] = ir[lane + i*32];
        s += v[i].x + v[i].y + v[i].z + v[i].w;
    }
    s = wsum(s);
    float mu = s * (1.0f / D);
    float q = 0.f;
    #pragma unroll
    for (int i = 0; i < V; i++){
        float dx;
        dx = v[i].x - mu; q += dx*dx;
        dx = v[i].y - mu; q += dx*dx;
        dx = v[i].z - mu; q += dx*dx;
        dx = v[i].w - mu; q += dx*dx;
    }
    q = wsum(q);
    float rstd = rsqrtf(q * (1.0f / D) + 1e-5f);
    float4* orow = (float4*)(out + (size_t)row * D);
    #pragma unroll
    for (int i = 0; i < V; i++){
        float4 gg = ((const float4*)g)[lane + i*32];
        float4 bb = ((const float4*)b)[lane + i*32];
        float4 y;
        y.x = (v[i].x - mu) * rstd * gg.x + bb.x;
        y.y = (v[i].y - mu) * rstd * gg.y + bb.y;
        y.z = (v[i].z - mu) * rstd * gg.z + bb.z;
        y.w = (v[i].w - mu) * rstd * gg.w + bb.w;
        orow[lane + i*32] = y;
    }
}

// ---------------- tf32 tensor-core GEMM: C[n,m] = A[n,k] @ B[k,m] ----------------
#define GBM 128
#define GBN 64
#define GBK 32
#define AS_STRIDE (GBK + 4)
#define BS_STRIDE (GBN + 4)

__global__ void __launch_bounds__(256, 2) gemm_tf32(const float* __restrict__ A,
                                                    const float* __restrict__ B,
                                                    float* __restrict__ C,
                                                    int n, int k, int m){
    __shared__ float As[GBM][AS_STRIDE];
    __shared__ float Bs[GBK][BS_STRIDE];

    int tid  = threadIdx.x;
    int wid  = tid >> 5;
    int lane = tid & 31;
    int wm   = (wid & 3) * 32;
    int wn   = (wid >> 2) * 32;
    int grp  = lane >> 2;
    int tg   = lane & 3;

    int bm = blockIdx.y * GBM;
    int bn = blockIdx.x * GBN;

    float acc[2][4][4];
    #pragma unroll
    for (int i=0;i<2;i++)
        #pragma unroll
        for (int j=0;j<4;j++)
            #pragma unroll
            for (int l=0;l<4;l++) acc[i][j][l] = 0.f;

    int arow  = tid >> 3;
    int acol  = (tid & 7) * 4;
    int brow  = tid >> 4;
    int bcol  = (tid & 15) * 4;

    for (int k0 = 0; k0 < k; k0 += GBK){
        #pragma unroll
        for (int i = 0; i < 4; i++){
            int row = arow + i*32;
            float4 v = make_float4(0,0,0,0);
            int gr = bm + row;
            if (gr < n) v = *(const float4*)&A[(size_t)gr * k + k0 + acol];
            As[row][acol+0] = __uint_as_float(tf32_of(v.x));
            As[row][acol+1] = __uint_as_float(tf32_of(v.y));
            As[row][acol+2] = __uint_as_float(tf32_of(v.z));
            As[row][acol+3] = __uint_as_float(tf32_of(v.w));
        }
        #pragma unroll
        for (int i = 0; i < 2; i++){
            int row = brow + i*16;
            float4 v = *(const float4*)&B[(size_t)(k0 + row) * m + bn + bcol];
            Bs[row][bcol+0] = __uint_as_float(tf32_of(v.x));
            Bs[row][bcol+1] = __uint_as_float(tf32_of(v.y));
            Bs[row][bcol+2] = __uint_as_float(tf32_of(v.z));
            Bs[row][bcol+3] = __uint_as_float(tf32_of(v.w));
        }
        __syncthreads();

        #pragma unroll
        for (int kk = 0; kk < 4; kk++){
            unsigned a[2][4], bfr[4][2];
            #pragma unroll
            for (int mt = 0; mt < 2; mt++){
                int r = wm + mt*16 + grp;
                int c = kk*8 + tg;
                a[mt][0] = __float_as_uint(As[r    ][c    ]);
                a[mt][1] = __float_as_uint(As[r + 8][c    ]);
                a[mt][2] = __float_as_uint(As[r    ][c + 4]);
                a[mt][3] = __float_as_uint(As[r + 8][c + 4]);
            }
            #pragma unroll
            for (int nt = 0; nt < 4; nt++){
                int c = wn + nt*8 + grp;
                int r = kk*8 + tg;
                bfr[nt][0] = __float_as_uint(Bs[r    ][c]);
                bfr[nt][1] = __float_as_uint(Bs[r + 4][c]);
            }
            #pragma unroll
            for (int mt = 0; mt < 2; mt++)
                #pragma unroll
                for (int nt = 0; nt < 4; nt++){
                    asm volatile(
                        "mma.sync.aligned.m16n8k8.row.col.f32.tf32.tf32.f32 "
                        "{%0,%1,%2,%3}, {%4,%5,%6,%7}, {%8,%9}, {%0,%1,%2,%3};"
                        : "+f"(acc[mt][nt][0]), "+f"(acc[mt][nt][1]),
                          "+f"(acc[mt][nt][2]), "+f"(acc[mt][nt][3])
                        : "r"(a[mt][0]), "r"(a[mt][1]), "r"(a[mt][2]), "r"(a[mt][3]),
                          "r"(bfr[nt][0]), "r"(bfr[nt][1]));
                }
        }
        __syncthreads();
    }

    #pragma unroll
    for (int mt = 0; mt < 2; mt++){
        int r0 = bm + wm + mt*16 + grp;
        int r1 = r0 + 8;
        #pragma unroll
        for (int nt = 0; nt < 4; nt++){
            int c = bn + wn + nt*8 + 2*tg;
            if (r0 < n) *(float2*)&C[(size_t)r0 * m + c] = make_float2(acc[mt][nt][0], acc[mt][nt][1]);
            if (r1 < n) *(float2*)&C[(size_t)r1 * m + c] = make_float2(acc[mt][nt][2], acc[mt][nt][3]);
        }
    }
}

// ---------------- attention logits per node ----------------
template<int H>
__global__ void attn_logits(const float* __restrict__ xh, const float* __restrict__ as_,
                            const float* __restrict__ ad_, float* __restrict__ als,
                            float* __restrict__ ald){
    int w = (blockIdx.x * blockDim.x + threadIdx.x) >> 5;
    if (w >= Nn * H) return;
    int lane = threadIdx.x & 31;
    int h = w % H;
    const float4* xr = (const float4*)(xh + (size_t)w * HIDC);
    float4 x  = xr[lane];
    float4 sv = ((const float4*)(as_ + h * HIDC))[lane];
    float4 dv = ((const float4*)(ad_ + h * HIDC))[lane];
    float s = x.x*sv.x + x.y*sv.y + x.z*sv.z + x.w*sv.w;
    float d = x.x*dv.x + x.y*dv.y + x.z*dv.z + x.w*dv.w;
    s = wsum(s); d = wsum(d);
    if (lane == 0){ als[w] = s; ald[w] = d; }
}

// ------ GAT agg H=4: TWO warps per node (2 heads each) + bias+LN+GELU -> h1 ------
// 256 threads = 8 warps = 4 nodes per block. Nn % 4 == 0, so no stragglers.
__global__ void __launch_bounds__(256) gat_agg4_fused(const float4* __restrict__ als4,
                                                      const float4* __restrict__ ald4,
                                                      const float* __restrict__ xh,
                                                      const float* __restrict__ bias,
                                                      const float* __restrict__ gw,
                                                      const float* __restrict__ bw,
                                                      float* __restrict__ h1){
    __shared__ float s_part[8], q_part[8];
    int wib  = threadIdx.x >> 5;            // warp in block 0..7
    int node = blockIdx.x * 4 + (wib >> 1);
    int sub  = wib & 1;                     // 0: heads 0,1   1: heads 2,3
    int lane = threadIdx.x & 31;

    float4 adv = ald4[node];
    float ad0 = sub ? adv.z : adv.x;
    float ad1 = sub ? adv.w : adv.y;
    int pbeg = g_rowptr[node], pend = g_rowptr[node+1];

    // phase A: max for this warp's 2 heads (lane-parallel)
    float m0 = -1e30f, m1 = -1e30f;
    for (int p = pbeg + lane; p < pend; p += 32){
        float4 as = als4[g_csr_src[p]];
        float s0 = sub ? as.z : as.x;
        float s1 = sub ? as.w : as.y;
        m0 = fmaxf(m0, lrelu(s0 + ad0));
        m1 = fmaxf(m1, lrelu(s1 + ad1));
    }
    m0 = wmax(m0); m1 = wmax(m1);

    // phase B: denominators
    float d0 = 0.f, d1 = 0.f;
    for (int p = pbeg + lane; p < pend; p += 32){
        float4 as = als4[g_csr_src[p]];
        float s0 = sub ? as.z : as.x;
        float s1 = sub ? as.w : as.y;
        d0 += __expf(lrelu(s0 + ad0) - m0);
        d1 += __expf(lrelu(s1 + ad1) - m1);
    }
    d0 = wsum(d0); d1 = wsum(d1);
    float r0 = 1.f/d0, r1 = 1.f/d1;

    // phase C: feature accumulation for 2 heads (independent iterations)
    float4 a0 = make_float4(0,0,0,0), a1 = a0;
    #pragma unroll 4
    for (int p = pbeg; p < pend; p++){
        int s = g_csr_src[p];
        float4 as = als4[s];
        float s0 = sub ? as.z : as.x;
        float s1 = sub ? as.w : as.y;
        const float4* xr = (const float4*)(xh + (size_t)s * F1) + sub*64;
        float4 x0 = xr[lane];
        float4 x1 = xr[32 + lane];
        float e0 = __expf(lrelu(s0 + ad0) - m0);
        float e1 = __expf(lrelu(s1 + ad1) - m1);
        a0.x += e0*x0.x; a0.y += e0*x0.y; a0.z += e0*x0.z; a0.w += e0*x0.w;
        a1.x += e1*x1.x; a1.y += e1*x1.y; a1.z += e1*x1.z; a1.w += e1*x1.w;
    }

    // epilogue: bias; cross-warp LN over 512; gelu; write this warp's half
    const float4* b4 = (const float4*)bias + sub*64;
    float4 q0 = b4[lane], q1 = b4[32 + lane];
    float4 v0, v1;
    v0.x = a0.x*r0 + q0.x; v0.y = a0.y*r0 + q0.y; v0.z = a0.z*r0 + q0.z; v0.w = a0.w*r0 + q0.w;
    v1.x = a1.x*r1 + q1.x; v1.y = a1.y*r1 + q1.y; v1.z = a1.z*r1 + q1.z; v1.w = a1.w*r1 + q1.w;

    float s = wsum(v0.x+v0.y+v0.z+v0.w + v1.x+v1.y+v1.z+v1.w);
    if (lane == 0) s_part[wib] = s;
    __syncthreads();
    int base = wib & ~1;
    float mu = (s_part[base] + s_part[base+1]) * (1.0f / F1);

    float q = 0.f, dx;
    dx=v0.x-mu; q+=dx*dx; dx=v0.y-mu; q+=dx*dx; dx=v0.z-mu; q+=dx*dx; dx=v0.w-mu; q+=dx*dx;
    dx=v1.x-mu; q+=dx*dx; dx=v1.y-mu; q+=dx*dx; dx=v1.z-mu; q+=dx*dx; dx=v1.w-mu; q+=dx*dx;
    q = wsum(q);
    if (lane == 0) q_part[wib] = q;
    __syncthreads();
    float rstd = rsqrtf((q_part[base] + q_part[base+1]) * (1.0f / F1) + 1e-5f);

    const float4* g4 = (const float4*)gw + sub*64;
    const float4* w4 = (const float4*)bw + sub*64;
    float4* orow = (float4*)(h1 + (size_t)node * F1) + sub*64;
    float4 gg = g4[lane],      bb = w4[lane];
    float4 y;
    y.x = gelu_exact((v0.x - mu) * rstd * gg.x + bb.x);
    y.y = gelu_exact((v0.y - mu) * rstd * gg.y + bb.y);
    y.z = gelu_exact((v0.z - mu) * rstd * gg.z + bb.z);
    y.w = gelu_exact((v0.w - mu) * rstd * gg.w + bb.w);
    orow[lane] = y;
    gg = g4[32 + lane]; bb = w4[32 + lane];
    y.x = gelu_exact((v1.x - mu) * rstd * gg.x + bb.x);
    y.y = gelu_exact((v1.y - mu) * rstd * gg.y + bb.y);
    y.z = gelu_exact((v1.z - mu) * rstd * gg.z + bb.z);
    y.w = gelu_exact((v1.w - mu) * rstd * gg.w + bb.w);
    orow[32 + lane] = y;
}

// ------- GAT agg H=1 + bias + LN + GELU + out-projection + log_softmax -> out -------
__global__ void __launch_bounds__(256) gat_agg1_fused(const float* __restrict__ als,
                                                      const float* __restrict__ ald,
                                                      const float* __restrict__ xh,
                                                      const float* __restrict__ bias,
                                                      const float* __restrict__ gw,
                                                      const float* __restrict__ bw,
                                                      const float* __restrict__ Wo,
                                                      const float* __restrict__ bo,
                                                      float* __restrict__ out){
    int node = blockIdx.x * (blockDim.x >> 5) + (threadIdx.x >> 5);
    if (node >= Nn) return;
    int lane = threadIdx.x & 31;
    float ad = ald[node];
    int pbeg = g_rowptr[node], pend = g_rowptr[node+1];

    float m = -1e30f;
    for (int p = pbeg + lane; p < pend; p += 32)
        m = fmaxf(m, lrelu(als[g_csr_src[p]] + ad));
    m = wmax(m);

    float den = 0.f;
    for (int p = pbeg + lane; p < pend; p += 32)
        den += __expf(lrelu(als[g_csr_src[p]] + ad) - m);
    den = wsum(den);
    float r = 1.f/den;

    float4 acc = make_float4(0,0,0,0);
    #pragma unroll 2
    for (int p = pbeg; p < pend; p++){
        int s = g_csr_src[p];
        float e = __expf(lrelu(als[s] + ad) - m);
        float4 xv = ((const float4*)(xh + (size_t)s * HIDC))[lane];
        acc.x += e*xv.x; acc.y += e*xv.y; acc.z += e*xv.z; acc.w += e*xv.w;
    }

    // bias + LN(128) + GELU, kept in registers
    float4 qb = ((const float4*)bias)[lane];
    float4 v;
    v.x = acc.x*r + qb.x; v.y = acc.y*r + qb.y; v.z = acc.z*r + qb.z; v.w = acc.w*r + qb.w;
    float s = wsum(v.x + v.y + v.z + v.w);
    float mu = s * (1.0f / HIDC);
    float q = 0.f, dx;
    dx=v.x-mu; q+=dx*dx; dx=v.y-mu; q+=dx*dx; dx=v.z-mu; q+=dx*dx; dx=v.w-mu; q+=dx*dx;
    q = wsum(q);
    float rstd = rsqrtf(q * (1.0f / HIDC) + 1e-5f);
    float4 gg = ((const float4*)gw)[lane];
    float4 bb = ((const float4*)bw)[lane];
    float4 y;
    y.x = gelu_exact((v.x - mu) * rstd * gg.x + bb.x);
    y.y = gelu_exact((v.y - mu) * rstd * gg.y + bb.y);
    y.z = gelu_exact((v.z - mu) * rstd * gg.z + bb.z);
    y.w = gelu_exact((v.w - mu) * rstd * gg.w + bb.w);

    // fused output projection: z[lane] = bo[lane] + sum_k y_k * Wo[k][lane]
    float z = bo[lane];
    #pragma unroll 8
    for (int k4 = 0; k4 < 32; k4++){
        float yx = __shfl_sync(0xffffffffu, y.x, k4);
        float yy = __shfl_sync(0xffffffffu, y.y, k4);
        float yz = __shfl_sync(0xffffffffu, y.z, k4);
        float yw = __shfl_sync(0xffffffffu, y.w, k4);
        const float* wr = Wo + k4*4*DOUT + lane;
        z += yx*wr[0] + yy*wr[DOUT] + yz*wr[2*DOUT] + yw*wr[3*DOUT];
    }
    float mx = wmax(z);
    float ex = expf(z - mx);
    float sm = wsum(ex);
    out[(size_t)node * DOUT + lane] = z - mx - logf(sm);
}

// ---------------- launch ----------------
extern "C" void kernel_launch(void* const* d_in, const int* in_sizes, int n_in,
                              void* d_out, int out_size){
    const float* x      = (const float*)d_in[0];
    const void*  ei     = d_in[1];
    const float* g_in   = (const float*)d_in[2];
    const float* b_in   = (const float*)d_in[3];
    const float* W1     = (const float*)d_in[4];
    const float* att1_s = (const float*)d_in[5];
    const float* att1_d = (const float*)d_in[6];
    const float* bias1  = (const float*)d_in[7];
    const float* g1     = (const float*)d_in[8];
    const float* b1     = (const float*)d_in[9];
    const float* W2     = (const float*)d_in[10];
    const float* att2_s = (const float*)d_in[11];
    const float* att2_d = (const float*)d_in[12];
    const float* bias2  = (const float*)d_in[13];
    const float* g2     = (const float*)d_in[14];
    const float* b2     = (const float*)d_in[15];
    const float* Wo     = (const float*)d_in[16];
    const float* bo     = (const float*)d_in[17];
    float* out = (float*)d_out;

    void *p_h0, *p_xh1, *p_al1s, *p_al1d, *p_h1;
    void *p_xh2, *p_al2s, *p_al2d, *p_is32, *p_deg;
    cudaGetSymbolAddress(&p_h0,   g_h0);
    cudaGetSymbolAddress(&p_xh1,  g_xh1);
    cudaGetSymbolAddress(&p_al1s, g_al1s);
    cudaGetSymbolAddress(&p_al1d, g_al1d);
    cudaGetSymbolAddress(&p_h1,   g_h1);
    cudaGetSymbolAddress(&p_xh2,  g_xh2);
    cudaGetSymbolAddress(&p_al2s, g_al2s);
    cudaGetSymbolAddress(&p_al2d, g_al2d);
    cudaGetSymbolAddress(&p_is32, g_is32);
    cudaGetSymbolAddress(&p_deg,  g_deg);

    const int T = 256;
    const int warpsPB = T / 32;

    // ---- side stream for CSR build (fork/join via events; capture-legal) ----
    cudaStream_t s2;
    cudaStreamCreate(&s2);
    cudaEvent_t evF, evJ;
    cudaEventCreateWithFlags(&evF, cudaEventDisableTiming);
    cudaEventCreateWithFlags(&evJ, cudaEventDisableTiming);

    cudaEventRecord(evF, 0);
    cudaStreamWaitEvent(s2, evF, 0);

    cudaMemsetAsync(p_is32, 0, sizeof(int), s2);
    cudaMemsetAsync(p_deg,  0, Nn * sizeof(int), s2);
    detect_dtype<<<16, 256, 0, s2>>>((const long long*)ei);
    decode_edges<<<(ETOT + T - 1)/T, T, 0, s2>>>((const int*)ei);
    scan_tiles<<<NTILES, 256, 0, s2>>>();
    scan_sums<<<1, 128, 0, s2>>>();
    scan_finalize<<<NTILES, 256, 0, s2>>>();
    build_csr<<<(ETOT + T - 1)/T, T, 0, s2>>>();
    cudaEventRecord(evJ, s2);

    // ---- dense path on main stream ----
    ln_kernel<128><<<(Nn + warpsPB - 1)/warpsPB, T>>>(x, g_in, b_in, (float*)p_h0);
    {
        dim3 grid(F1/GBN, (Nn + GBM - 1)/GBM);
        gemm_tf32<<<grid, 256>>>((const float*)p_h0, W1, (float*)p_xh1, Nn, DIN, F1);
    }
    attn_logits<NH1><<<(Nn*NH1 + warpsPB - 1)/warpsPB, T>>>((const float*)p_xh1, att1_s, att1_d,
                                                            (float*)p_al1s, (float*)p_al1d);

    // join CSR before aggregation
    cudaStreamWaitEvent(0, evJ, 0);

    gat_agg4_fused<<<Nn/4, T>>>((const float4*)p_al1s, (const float4*)p_al1d,
                                (const float*)p_xh1, bias1, g1, b1, (float*)p_h1);

    {
        dim3 grid(HIDC/GBN, (Nn + GBM - 1)/GBM);
        gemm_tf32<<<grid, 256>>>((const float*)p_h1, W2, (float*)p_xh2, Nn, F1, HIDC);
    }
    attn_logits<1><<<(Nn + warpsPB - 1)/warpsPB, T>>>((const float*)p_xh2, att2_s, att2_d,
                                                      (float*)p_al2s, (float*)p_al2d);
    gat_agg1_fused<<<(Nn + warpsPB - 1)/warpsPB, T>>>((const float*)p_al2s, (const float*)p_al2d,
                                                      (const float*)p_xh2, bias2, g2, b2,
                                                      Wo, bo, out);
}

// round 12
// speedup vs baseline: 1.4666x; 1.0283x over previous
#include <cuda_runtime.h>
#include <cuda_fp16.h>
#include <math.h>
#include <limits.h>

#define Nn    20000
#define Ee    320000
#define ETOT  340000   // Ee + Nn self loops
#define DIN   128
#define HIDC  128
#define NH1   4
#define F1    512      // NH1*HIDC
#define DOUT  32
#define NTILES ((Nn + 255) / 256)   // 79

// ---------------- scratch (device globals; allocation-free) ----------------
__device__ __align__(16) float  g_h0  [Nn*DIN];
__device__ __align__(16) __half g_xh1 [(size_t)Nn*F1];
__device__ __align__(16) float  g_al1s[Nn*NH1];
__device__ __align__(16) float  g_al1d[Nn*NH1];
__device__ __align__(16) float  g_h1  [(size_t)Nn*F1];
__device__ __align__(16) __half g_xh2 [Nn*HIDC];
__device__              float   g_al2s[Nn];
__device__              float   g_al2d[Nn];
__device__              int     g_src [ETOT];
__device__              int     g_dst [ETOT];
__device__              int     g_deg [Nn];
__device__              int     g_scantmp[Nn];
__device__              int     g_tilesum[128];
__device__              int     g_tileoff[128];
__device__              int     g_rowptr[Nn+1];
__device__              int     g_cursor[Nn];
__device__              int     g_csr_src[ETOT];
__device__              int     g_is32;

// ---------------- helpers ----------------
__device__ __forceinline__ float wsum(float v){
    #pragma unroll
    for (int o = 16; o; o >>= 1) v += __shfl_xor_sync(0xffffffffu, v, o);
    return v;
}
__device__ __forceinline__ float wmax(float v){
    #pragma unroll
    for (int o = 16; o; o >>= 1) v = fmaxf(v, __shfl_xor_sync(0xffffffffu, v, o));
    return v;
}
__device__ __forceinline__ float gelu_exact(float x){
    return 0.5f * x * (1.0f + erff(x * 0.70710678118654752f));
}
__device__ __forceinline__ unsigned tf32_of(float x){
    unsigned u; asm("cvt.rna.tf32.f32 %0, %1;" : "=r"(u) : "f"(x)); return u;
}
__device__ __forceinline__ float lrelu(float x){ return x > 0.f ? x : 0.2f * x; }

__device__ __forceinline__ float4 h4_to_f4(uint2 u){
    __half2 lo = *reinterpret_cast<__half2*>(&u.x);
    __half2 hi = *reinterpret_cast<__half2*>(&u.y);
    float2 a = __half22float2(lo), b = __half22float2(hi);
    return make_float4(a.x, a.y, b.x, b.y);
}

// ---------------- edge dtype detection + decode (+degree count) ----------------
__global__ void detect_dtype(const long long* __restrict__ p){
    long long stride = (2LL * Ee) / 4096;
    if (stride < 1) stride = 1;
    long long idx = (long long)(blockIdx.x * blockDim.x + threadIdx.x) * stride;
    if (idx >= 2LL * Ee) return;
    long long v = p[idx];
    if (v < 0 || v >= Nn) atomicExch(&g_is32, 1);
}

__global__ void decode_edges(const int* __restrict__ p32){
    int e = blockIdx.x * blockDim.x + threadIdx.x;
    if (e >= ETOT) return;
    int s, d;
    if (e < Ee){
        if (g_is32){ s = p32[e];   d = p32[Ee + e]; }
        else       { s = p32[2*e]; d = p32[2*Ee + 2*e]; }
    } else {
        s = d = e - Ee;
    }
    g_src[e] = s; g_dst[e] = d;
    atomicAdd(&g_deg[d], 1);
}

// ---------------- parallel 3-kernel scan of g_deg -> g_rowptr ----------------
__global__ void scan_tiles(){
    __shared__ int sh[256];
    int i = blockIdx.x * 256 + threadIdx.x;
    int v = (i < Nn) ? g_deg[i] : 0;
    sh[threadIdx.x] = v;
    __syncthreads();
    for (int off = 1; off < 256; off <<= 1){
        int t = (threadIdx.x >= off) ? sh[threadIdx.x - off] : 0;
        __syncthreads();
        sh[threadIdx.x] += t;
        __syncthreads();
    }
    if (i < Nn) g_scantmp[i] = sh[threadIdx.x];
    if (threadIdx.x == 255) g_tilesum[blockIdx.x] = sh[255];
}

__global__ void scan_sums(){
    __shared__ int sh[128];
    int t = threadIdx.x;
    sh[t] = (t < NTILES) ? g_tilesum[t] : 0;
    __syncthreads();
    for (int off = 1; off < 128; off <<= 1){
        int v = (t >= off) ? sh[t - off] : 0;
        __syncthreads();
        sh[t] += v;
        __syncthreads();
    }
    if (t < NTILES) g_tileoff[t] = (t == 0) ? 0 : sh[t - 1];
}

__global__ void scan_finalize(){
    int i = blockIdx.x * 256 + threadIdx.x;
    if (i >= Nn) return;
    int r = g_scantmp[i] - g_deg[i] + g_tileoff[i >> 8];
    g_rowptr[i] = r;
    g_cursor[i] = r;
    if (i == 0) g_rowptr[Nn] = ETOT;
}

__global__ void build_csr(){
    int e = blockIdx.x * blockDim.x + threadIdx.x;
    if (e >= ETOT) return;
    int pos = atomicAdd(&g_cursor[g_dst[e]], 1);
    g_csr_src[pos] = g_src[e];
}

// ---------------- standalone LayerNorm (input only) ----------------
template<int D>
__global__ void ln_kernel(const float* __restrict__ in, const float* __restrict__ g,
                          const float* __restrict__ b, float* __restrict__ out){
    int row = blockIdx.x * (blockDim.x >> 5) + (threadIdx.x >> 5);
    if (row >= Nn) return;
    int lane = threadIdx.x & 31;
    constexpr int V = D / 128;
    float4 v[V];
    const float4* ir = (const float4*)(in + (size_t)row * D);
    float s = 0.f;
    #pragma unroll
    for (int i = 0; i < V; i++){
        v[i] = ir[lane + i*32];
        s += v[i].x + v[i].y + v[i].z + v[i].w;
    }
    s = wsum(s);
    float mu = s * (1.0f / D);
    float q = 0.f;
    #pragma unroll
    for (int i = 0; i < V; i++){
        float dx;
        dx = v[i].x - mu; q += dx*dx;
        dx = v[i].y - mu; q += dx*dx;
        dx = v[i].z - mu; q += dx*dx;
        dx = v[i].w - mu; q += dx*dx;
    }
    q = wsum(q);
    float rstd = rsqrtf(q * (1.0f / D) + 1e-5f);
    float4* orow = (float4*)(out + (size_t)row * D);
    #pragma unroll
    for (int i = 0; i < V; i++){
        float4 gg = ((const float4*)g)[lane + i*32];
        float4 bb = ((const float4*)b)[lane + i*32];
        float4 y;
        y.x = (v[i].x - mu) * rstd * gg.x + bb.x;
        y.y = (v[i].y - mu) * rstd * gg.y + bb.y;
        y.z = (v[i].z - mu) * rstd * gg.z + bb.z;
        y.w = (v[i].w - mu) * rstd * gg.w + bb.w;
        orow[lane + i*32] = y;
    }
}

// ---------------- tf32 tensor-core GEMM: C[n,m](fp16) = A[n,k] @ B[k,m] ----------------
#define GBM 128
#define GBN 64
#define GBK 32
#define AS_STRIDE (GBK + 4)
#define BS_STRIDE (GBN + 4)

__global__ void __launch_bounds__(256, 2) gemm_tf32(const float* __restrict__ A,
                                                    const float* __restrict__ B,
                                                    __half* __restrict__ C,
                                                    int n, int k, int m){
    __shared__ float As[GBM][AS_STRIDE];
    __shared__ float Bs[GBK][BS_STRIDE];

    int tid  = threadIdx.x;
    int wid  = tid >> 5;
    int lane = tid & 31;
    int wm   = (wid & 3) * 32;
    int wn   = (wid >> 2) * 32;
    int grp  = lane >> 2;
    int tg   = lane & 3;

    int bm = blockIdx.y * GBM;
    int bn = blockIdx.x * GBN;

    float acc[2][4][4];
    #pragma unroll
    for (int i=0;i<2;i++)
        #pragma unroll
        for (int j=0;j<4;j++)
            #pragma unroll
            for (int l=0;l<4;l++) acc[i][j][l] = 0.f;

    int arow  = tid >> 3;
    int acol  = (tid & 7) * 4;
    int brow  = tid >> 4;
    int bcol  = (tid & 15) * 4;

    for (int k0 = 0; k0 < k; k0 += GBK){
        #pragma unroll
        for (int i = 0; i < 4; i++){
            int row = arow + i*32;
            float4 v = make_float4(0,0,0,0);
            int gr = bm + row;
            if (gr < n) v = *(const float4*)&A[(size_t)gr * k + k0 + acol];
            As[row][acol+0] = __uint_as_float(tf32_of(v.x));
            As[row][acol+1] = __uint_as_float(tf32_of(v.y));
            As[row][acol+2] = __uint_as_float(tf32_of(v.z));
            As[row][acol+3] = __uint_as_float(tf32_of(v.w));
        }
        #pragma unroll
        for (int i = 0; i < 2; i++){
            int row = brow + i*16;
            float4 v = *(const float4*)&B[(size_t)(k0 + row) * m + bn + bcol];
            Bs[row][bcol+0] = __uint_as_float(tf32_of(v.x));
            Bs[row][bcol+1] = __uint_as_float(tf32_of(v.y));
            Bs[row][bcol+2] = __uint_as_float(tf32_of(v.z));
            Bs[row][bcol+3] = __uint_as_float(tf32_of(v.w));
        }
        __syncthreads();

        #pragma unroll
        for (int kk = 0; kk < 4; kk++){
            unsigned a[2][4], bfr[4][2];
            #pragma unroll
            for (int mt = 0; mt < 2; mt++){
                int r = wm + mt*16 + grp;
                int c = kk*8 + tg;
                a[mt][0] = __float_as_uint(As[r    ][c    ]);
                a[mt][1] = __float_as_uint(As[r + 8][c    ]);
                a[mt][2] = __float_as_uint(As[r    ][c + 4]);
                a[mt][3] = __float_as_uint(As[r + 8][c + 4]);
            }
            #pragma unroll
            for (int nt = 0; nt < 4; nt++){
                int c = wn + nt*8 + grp;
                int r = kk*8 + tg;
                bfr[nt][0] = __float_as_uint(Bs[r    ][c]);
                bfr[nt][1] = __float_as_uint(Bs[r + 4][c]);
            }
            #pragma unroll
            for (int mt = 0; mt < 2; mt++)
                #pragma unroll
                for (int nt = 0; nt < 4; nt++){
                    asm volatile(
                        "mma.sync.aligned.m16n8k8.row.col.f32.tf32.tf32.f32 "
                        "{%0,%1,%2,%3}, {%4,%5,%6,%7}, {%8,%9}, {%0,%1,%2,%3};"
                        : "+f"(acc[mt][nt][0]), "+f"(acc[mt][nt][1]),
                          "+f"(acc[mt][nt][2]), "+f"(acc[mt][nt][3])
                        : "r"(a[mt][0]), "r"(a[mt][1]), "r"(a[mt][2]), "r"(a[mt][3]),
                          "r"(bfr[nt][0]), "r"(bfr[nt][1]));
                }
        }
        __syncthreads();
    }

    #pragma unroll
    for (int mt = 0; mt < 2; mt++){
        int r0 = bm + wm + mt*16 + grp;
        int r1 = r0 + 8;
        #pragma unroll
        for (int nt = 0; nt < 4; nt++){
            int c = bn + wn + nt*8 + 2*tg;
            if (r0 < n) *(__half2*)&C[(size_t)r0 * m + c] = __floats2half2_rn(acc[mt][nt][0], acc[mt][nt][1]);
            if (r1 < n) *(__half2*)&C[(size_t)r1 * m + c] = __floats2half2_rn(acc[mt][nt][2], acc[mt][nt][3]);
        }
    }
}

// ---------------- attention logits per node (fp16 features) ----------------
template<int H>
__global__ void attn_logits(const __half* __restrict__ xh, const float* __restrict__ as_,
                            const float* __restrict__ ad_, float* __restrict__ als,
                            float* __restrict__ ald){
    int w = (blockIdx.x * blockDim.x + threadIdx.x) >> 5;
    if (w >= Nn * H) return;
    int lane = threadIdx.x & 31;
    int h = w % H;
    float4 x = h4_to_f4(((const uint2*)(xh + (size_t)w * HIDC))[lane]);
    float4 sv = ((const float4*)(as_ + h * HIDC))[lane];
    float4 dv = ((const float4*)(ad_ + h * HIDC))[lane];
    float s = x.x*sv.x + x.y*sv.y + x.z*sv.z + x.w*sv.w;
    float d = x.x*dv.x + x.y*dv.y + x.z*dv.z + x.w*dv.w;
    s = wsum(s); d = wsum(d);
    if (lane == 0){ als[w] = s; ald[w] = d; }
}

// ------ GAT agg H=4: TWO warps per node (2 heads each), fp16 features ------
__global__ void __launch_bounds__(256) gat_agg4_fused(const float4* __restrict__ als4,
                                                      const float4* __restrict__ ald4,
                                                      const __half* __restrict__ xh,
                                                      const float* __restrict__ bias,
                                                      const float* __restrict__ gw,
                                                      const float* __restrict__ bw,
                                                      float* __restrict__ h1){
    __shared__ float s_part[8], q_part[8];
    int wib  = threadIdx.x >> 5;
    int node = blockIdx.x * 4 + (wib >> 1);
    int sub  = wib & 1;
    int lane = threadIdx.x & 31;

    float4 adv = ald4[node];
    float ad0 = sub ? adv.z : adv.x;
    float ad1 = sub ? adv.w : adv.y;
    int pbeg = g_rowptr[node], pend = g_rowptr[node+1];

    // phase A: max
    float m0 = -1e30f, m1 = -1e30f;
    for (int p = pbeg + lane; p < pend; p += 32){
        float4 as = als4[g_csr_src[p]];
        float s0 = sub ? as.z : as.x;
        float s1 = sub ? as.w : as.y;
        m0 = fmaxf(m0, lrelu(s0 + ad0));
        m1 = fmaxf(m1, lrelu(s1 + ad1));
    }
    m0 = wmax(m0); m1 = wmax(m1);

    // phase B: denominators
    float d0 = 0.f, d1 = 0.f;
    for (int p = pbeg + lane; p < pend; p += 32){
        float4 as = als4[g_csr_src[p]];
        float s0 = sub ? as.z : as.x;
        float s1 = sub ? as.w : as.y;
        d0 += __expf(lrelu(s0 + ad0) - m0);
        d1 += __expf(lrelu(s1 + ad1) - m1);
    }
    d0 = wsum(d0); d1 = wsum(d1);
    float r0 = 1.f/d0, r1 = 1.f/d1;

    // phase C: fp16 feature accumulation (independent iterations)
    float4 a0 = make_float4(0,0,0,0), a1 = a0;
    #pragma unroll 4
    for (int p = pbeg; p < pend; p++){
        int s = g_csr_src[p];
        float4 as = als4[s];
        float s0 = sub ? as.z : as.x;
        float s1 = sub ? as.w : as.y;
        const uint2* xr = (const uint2*)(xh + (size_t)s * F1) + sub*64;
        float4 x0 = h4_to_f4(xr[lane]);
        float4 x1 = h4_to_f4(xr[32 + lane]);
        float e0 = __expf(lrelu(s0 + ad0) - m0);
        float e1 = __expf(lrelu(s1 + ad1) - m1);
        a0.x += e0*x0.x; a0.y += e0*x0.y; a0.z += e0*x0.z; a0.w += e0*x0.w;
        a1.x += e1*x1.x; a1.y += e1*x1.y; a1.z += e1*x1.z; a1.w += e1*x1.w;
    }

    // epilogue: bias; cross-warp LN over 512; gelu; write this warp's half
    const float4* b4 = (const float4*)bias + sub*64;
    float4 q0 = b4[lane], q1 = b4[32 + lane];
    float4 v0, v1;
    v0.x = a0.x*r0 + q0.x; v0.y = a0.y*r0 + q0.y; v0.z = a0.z*r0 + q0.z; v0.w = a0.w*r0 + q0.w;
    v1.x = a1.x*r1 + q1.x; v1.y = a1.y*r1 + q1.y; v1.z = a1.z*r1 + q1.z; v1.w = a1.w*r1 + q1.w;

    float s = wsum(v0.x+v0.y+v0.z+v0.w + v1.x+v1.y+v1.z+v1.w);
    if (lane == 0) s_part[wib] = s;
    __syncthreads();
    int base = wib & ~1;
    float mu = (s_part[base] + s_part[base+1]) * (1.0f / F1);

    float q = 0.f, dx;
    dx=v0.x-mu; q+=dx*dx; dx=v0.y-mu; q+=dx*dx; dx=v0.z-mu; q+=dx*dx; dx=v0.w-mu; q+=dx*dx;
    dx=v1.x-mu; q+=dx*dx; dx=v1.y-mu; q+=dx*dx; dx=v1.z-mu; q+=dx*dx; dx=v1.w-mu; q+=dx*dx;
    q = wsum(q);
    if (lane == 0) q_part[wib] = q;
    __syncthreads();
    float rstd = rsqrtf((q_part[base] + q_part[base+1]) * (1.0f / F1) + 1e-5f);

    const float4* g4 = (const float4*)gw + sub*64;
    const float4* w4 = (const float4*)bw + sub*64;
    float4* orow = (float4*)(h1 + (size_t)node * F1) + sub*64;
    float4 gg = g4[lane],      bb = w4[lane];
    float4 y;
    y.x = gelu_exact((v0.x - mu) * rstd * gg.x + bb.x);
    y.y = gelu_exact((v0.y - mu) * rstd * gg.y + bb.y);
    y.z = gelu_exact((v0.z - mu) * rstd * gg.z + bb.z);
    y.w = gelu_exact((v0.w - mu) * rstd * gg.w + bb.w);
    orow[lane] = y;
    gg = g4[32 + lane]; bb = w4[32 + lane];
    y.x = gelu_exact((v1.x - mu) * rstd * gg.x + bb.x);
    y.y = gelu_exact((v1.y - mu) * rstd * gg.y + bb.y);
    y.z = gelu_exact((v1.z - mu) * rstd * gg.z + bb.z);
    y.w = gelu_exact((v1.w - mu) * rstd * gg.w + bb.w);
    orow[32 + lane] = y;
}

// ------- GAT agg H=1 (fp16) + bias + LN + GELU + out-projection + log_softmax -------
__global__ void __launch_bounds__(256) gat_agg1_fused(const float* __restrict__ als,
                                                      const float* __restrict__ ald,
                                                      const __half* __restrict__ xh,
                                                      const float* __restrict__ bias,
                                                      const float* __restrict__ gw,
                                                      const float* __restrict__ bw,
                                                      const float* __restrict__ Wo,
                                                      const float* __restrict__ bo,
                                                      float* __restrict__ out){
    int node = blockIdx.x * (blockDim.x >> 5) + (threadIdx.x >> 5);
    if (node >= Nn) return;
    int lane = threadIdx.x & 31;
    float ad = ald[node];
    int pbeg = g_rowptr[node], pend = g_rowptr[node+1];

    float m = -1e30f;
    for (int p = pbeg + lane; p < pend; p += 32)
        m = fmaxf(m, lrelu(als[g_csr_src[p]] + ad));
    m = wmax(m);

    float den = 0.f;
    for (int p = pbeg + lane; p < pend; p += 32)
        den += __expf(lrelu(als[g_csr_src[p]] + ad) - m);
    den = wsum(den);
    float r = 1.f/den;

    float4 acc = make_float4(0,0,0,0);
    #pragma unroll 2
    for (int p = pbeg; p < pend; p++){
        int s = g_csr_src[p];
        float e = __expf(lrelu(als[s] + ad) - m);
        float4 xv = h4_to_f4(((const uint2*)(xh + (size_t)s * HIDC))[lane]);
        acc.x += e*xv.x; acc.y += e*xv.y; acc.z += e*xv.z; acc.w += e*xv.w;
    }

    float4 qb = ((const float4*)bias)[lane];
    float4 v;
    v.x = acc.x*r + qb.x; v.y = acc.y*r + qb.y; v.z = acc.z*r + qb.z; v.w = acc.w*r + qb.w;
    float s = wsum(v.x + v.y + v.z + v.w);
    float mu = s * (1.0f / HIDC);
    float q = 0.f, dx;
    dx=v.x-mu; q+=dx*dx; dx=v.y-mu; q+=dx*dx; dx=v.z-mu; q+=dx*dx; dx=v.w-mu; q+=dx*dx;
    q = wsum(q);
    float rstd = rsqrtf(q * (1.0f / HIDC) + 1e-5f);
    float4 gg = ((const float4*)gw)[lane];
    float4 bb = ((const float4*)bw)[lane];
    float4 y;
    y.x = gelu_exact((v.x - mu) * rstd * gg.x + bb.x);
    y.y = gelu_exact((v.y - mu) * rstd * gg.y + bb.y);
    y.z = gelu_exact((v.z - mu) * rstd * gg.z + bb.z);
    y.w = gelu_exact((v.w - mu) * rstd * gg.w + bb.w);

    // fused output projection
    float z = bo[lane];
    #pragma unroll 8
    for (int k4 = 0; k4 < 32; k4++){
        float yx = __shfl_sync(0xffffffffu, y.x, k4);
        float yy = __shfl_sync(0xffffffffu, y.y, k4);
        float yz = __shfl_sync(0xffffffffu, y.z, k4);
        float yw = __shfl_sync(0xffffffffu, y.w, k4);
        const float* wr = Wo + k4*4*DOUT + lane;
        z += yx*wr[0] + yy*wr[DOUT] + yz*wr[2*DOUT] + yw*wr[3*DOUT];
    }
    float mx = wmax(z);
    float ex = expf(z - mx);
    float sm = wsum(ex);
    out[(size_t)node * DOUT + lane] = z - mx - logf(sm);
}

// ---------------- launch ----------------
extern "C" void kernel_launch(void* const* d_in, const int* in_sizes, int n_in,
                              void* d_out, int out_size){
    const float* x      = (const float*)d_in[0];
    const void*  ei     = d_in[1];
    const float* g_in   = (const float*)d_in[2];
    const float* b_in   = (const float*)d_in[3];
    const float* W1     = (const float*)d_in[4];
    const float* att1_s = (const float*)d_in[5];
    const float* att1_d = (const float*)d_in[6];
    const float* bias1  = (const float*)d_in[7];
    const float* g1     = (const float*)d_in[8];
    const float* b1     = (const float*)d_in[9];
    const float* W2     = (const float*)d_in[10];
    const float* att2_s = (const float*)d_in[11];
    const float* att2_d = (const float*)d_in[12];
    const float* bias2  = (const float*)d_in[13];
    const float* g2     = (const float*)d_in[14];
    const float* b2     = (const float*)d_in[15];
    const float* Wo     = (const float*)d_in[16];
    const float* bo     = (const float*)d_in[17];
    float* out = (float*)d_out;

    void *p_h0, *p_xh1, *p_al1s, *p_al1d, *p_h1;
    void *p_xh2, *p_al2s, *p_al2d, *p_is32, *p_deg;
    cudaGetSymbolAddress(&p_h0,   g_h0);
    cudaGetSymbolAddress(&p_xh1,  g_xh1);
    cudaGetSymbolAddress(&p_al1s, g_al1s);
    cudaGetSymbolAddress(&p_al1d, g_al1d);
    cudaGetSymbolAddress(&p_h1,   g_h1);
    cudaGetSymbolAddress(&p_xh2,  g_xh2);
    cudaGetSymbolAddress(&p_al2s, g_al2s);
    cudaGetSymbolAddress(&p_al2d, g_al2d);
    cudaGetSymbolAddress(&p_is32, g_is32);
    cudaGetSymbolAddress(&p_deg,  g_deg);

    const int T = 256;
    const int warpsPB = T / 32;

    // ---- side stream for CSR build (fork/join via events; capture-legal) ----
    cudaStream_t s2;
    cudaStreamCreate(&s2);
    cudaEvent_t evF, evJ;
    cudaEventCreateWithFlags(&evF, cudaEventDisableTiming);
    cudaEventCreateWithFlags(&evJ, cudaEventDisableTiming);

    cudaEventRecord(evF, 0);
    cudaStreamWaitEvent(s2, evF, 0);

    cudaMemsetAsync(p_is32, 0, sizeof(int), s2);
    cudaMemsetAsync(p_deg,  0, Nn * sizeof(int), s2);
    detect_dtype<<<16, 256, 0, s2>>>((const long long*)ei);
    decode_edges<<<(ETOT + T - 1)/T, T, 0, s2>>>((const int*)ei);
    scan_tiles<<<NTILES, 256, 0, s2>>>();
    scan_sums<<<1, 128, 0, s2>>>();
    scan_finalize<<<NTILES, 256, 0, s2>>>();
    build_csr<<<(ETOT + T - 1)/T, T, 0, s2>>>();
    cudaEventRecord(evJ, s2);

    // ---- dense path on main stream ----
    ln_kernel<128><<<(Nn + warpsPB - 1)/warpsPB, T>>>(x, g_in, b_in, (float*)p_h0);
    {
        dim3 grid(F1/GBN, (Nn + GBM - 1)/GBM);
        gemm_tf32<<<grid, 256>>>((const float*)p_h0, W1, (__half*)p_xh1, Nn, DIN, F1);
    }
    attn_logits<NH1><<<(Nn*NH1 + warpsPB - 1)/warpsPB, T>>>((const __half*)p_xh1, att1_s, att1_d,
                                                            (float*)p_al1s, (float*)p_al1d);

    // join CSR before aggregation
    cudaStreamWaitEvent(0, evJ, 0);

    gat_agg4_fused<<<Nn/4, T>>>((const float4*)p_al1s, (const float4*)p_al1d,
                                (const __half*)p_xh1, bias1, g1, b1, (float*)p_h1);

    {
        dim3 grid(HIDC/GBN, (Nn + GBM - 1)/GBM);
        gemm_tf32<<<grid, 256>>>((const float*)p_h1, W2, (__half*)p_xh2, Nn, F1, HIDC);
    }
    attn_logits<1><<<(Nn + warpsPB - 1)/warpsPB, T>>>((const __half*)p_xh2, att2_s, att2_d,
                                                      (float*)p_al2s, (float*)p_al2d);
    gat_agg1_fused<<<(Nn + warpsPB - 1)/warpsPB, T>>>((const float*)p_al2s, (const float*)p_al2d,
                                                      (const __half*)p_xh2, bias2, g2, b2,
                                                      Wo, bo, out);
}

// round 14
// speedup vs baseline: 1.4711x; 1.0031x over previous
#include <cuda_runtime.h>
#include <cuda_fp16.h>
#include <math.h>
#include <limits.h>

#define Nn    20000
#define Ee    320000
#define ETOT  340000   // Ee + Nn self loops
#define DIN   128
#define HIDC  128
#define NH1   4
#define F1    512      // NH1*HIDC
#define DOUT  32
#define NTILES ((Nn + 255) / 256)   // 79

// ---------------- scratch (device globals; allocation-free) ----------------
__device__ __align__(16) float  g_h0  [Nn*DIN];
__device__ __align__(16) __half g_xh1 [(size_t)Nn*F1];
__device__ __align__(16) float  g_al1s[Nn*NH1];
__device__ __align__(16) float  g_al1d[Nn*NH1];
__device__ __align__(16) float  g_h1  [(size_t)Nn*F1];
__device__ __align__(16) __half g_xh2 [Nn*HIDC];
__device__              float   g_al2s[Nn];
__device__              float   g_al2d[Nn];
__device__              int     g_src [ETOT];
__device__              int     g_dst [ETOT];
__device__              int     g_deg [Nn];
__device__              int     g_scantmp[Nn];
__device__              int     g_tilesum[128];
__device__              int     g_tileoff[128];
__device__              int     g_rowptr[Nn+1];
__device__              int     g_cursor[Nn];
__device__              int     g_csr_src[ETOT];
__device__              int     g_is32;

// ---------------- helpers ----------------
__device__ __forceinline__ float wsum(float v){
    #pragma unroll
    for (int o = 16; o; o >>= 1) v += __shfl_xor_sync(0xffffffffu, v, o);
    return v;
}
__device__ __forceinline__ float wmax(float v){
    #pragma unroll
    for (int o = 16; o; o >>= 1) v = fmaxf(v, __shfl_xor_sync(0xffffffffu, v, o));
    return v;
}
__device__ __forceinline__ float gelu_exact(float x){
    return 0.5f * x * (1.0f + erff(x * 0.70710678118654752f));
}
__device__ __forceinline__ unsigned tf32_of(float x){
    unsigned u; asm("cvt.rna.tf32.f32 %0, %1;" : "=r"(u) : "f"(x)); return u;
}
__device__ __forceinline__ float lrelu(float x){ return x > 0.f ? x : 0.2f * x; }

__device__ __forceinline__ float4 h4_to_f4(unsigned lo, unsigned hi){
    __half2 l = *reinterpret_cast<__half2*>(&lo);
    __half2 h = *reinterpret_cast<__half2*>(&hi);
    float2 a = __half22float2(l), b = __half22float2(h);
    return make_float4(a.x, a.y, b.x, b.y);
}

// exact warp-wide merge of per-lane (max, expsum) softmax states
__device__ __forceinline__ void softmax_merge(float& m, float& d){
    #pragma unroll
    for (int o = 16; o; o >>= 1){
        float om = __shfl_xor_sync(0xffffffffu, m, o);
        float od = __shfl_xor_sync(0xffffffffu, d, o);
        float nm = fmaxf(m, om);
        d = d*__expf(m - nm) + od*__expf(om - nm);
        m = nm;
    }
}
// lane-local online accumulate of value v into (m, d)
__device__ __forceinline__ void softmax_push(float& m, float& d, float v){
    float nm = fmaxf(m, v);
    d = d*__expf(m - nm) + __expf(v - nm);
    m = nm;
}

// ---------------- edge dtype detection + decode (+degree count) ----------------
__global__ void detect_dtype(const long long* __restrict__ p){
    long long stride = (2LL * Ee) / 4096;
    if (stride < 1) stride = 1;
    long long idx = (long long)(blockIdx.x * blockDim.x + threadIdx.x) * stride;
    if (idx >= 2LL * Ee) return;
    long long v = p[idx];
    if (v < 0 || v >= Nn) atomicExch(&g_is32, 1);
}

__global__ void decode_edges(const int* __restrict__ p32){
    int e = blockIdx.x * blockDim.x + threadIdx.x;
    if (e >= ETOT) return;
    int s, d;
    if (e < Ee){
        if (g_is32){ s = p32[e];   d = p32[Ee + e]; }
        else       { s = p32[2*e]; d = p32[2*Ee + 2*e]; }
    } else {
        s = d = e - Ee;
    }
    g_src[e] = s; g_dst[e] = d;
    atomicAdd(&g_deg[d], 1);
}

// ---------------- parallel 3-kernel scan of g_deg -> g_rowptr ----------------
__global__ void scan_tiles(){
    __shared__ int sh[256];
    int i = blockIdx.x * 256 + threadIdx.x;
    int v = (i < Nn) ? g_deg[i] : 0;
    sh[threadIdx.x] = v;
    __syncthreads();
    for (int off = 1; off < 256; off <<= 1){
        int t = (threadIdx.x >= off) ? sh[threadIdx.x - off] : 0;
        __syncthreads();
        sh[threadIdx.x] += t;
        __syncthreads();
    }
    if (i < Nn) g_scantmp[i] = sh[threadIdx.x];
    if (threadIdx.x == 255) g_tilesum[blockIdx.x] = sh[255];
}

__global__ void scan_sums(){
    __shared__ int sh[128];
    int t = threadIdx.x;
    sh[t] = (t < NTILES) ? g_tilesum[t] : 0;
    __syncthreads();
    for (int off = 1; off < 128; off <<= 1){
        int v = (t >= off) ? sh[t - off] : 0;
        __syncthreads();
        sh[t] += v;
        __syncthreads();
    }
    if (t < NTILES) g_tileoff[t] = (t == 0) ? 0 : sh[t - 1];
}

__global__ void scan_finalize(){
    int i = blockIdx.x * 256 + threadIdx.x;
    if (i >= Nn) return;
    int r = g_scantmp[i] - g_deg[i] + g_tileoff[i >> 8];
    g_rowptr[i] = r;
    g_cursor[i] = r;
    if (i == 0) g_rowptr[Nn] = ETOT;
}

__global__ void build_csr(){
    int e = blockIdx.x * blockDim.x + threadIdx.x;
    if (e >= ETOT) return;
    int pos = atomicAdd(&g_cursor[g_dst[e]], 1);
    g_csr_src[pos] = g_src[e];
}

// ---------------- standalone LayerNorm (input only) ----------------
template<int D>
__global__ void ln_kernel(const float* __restrict__ in, const float* __restrict__ g,
                          const float* __restrict__ b, float* __restrict__ out){
    int row = blockIdx.x * (blockDim.x >> 5) + (threadIdx.x >> 5);
    if (row >= Nn) return;
    int lane = threadIdx.x & 31;
    constexpr int V = D / 128;
    float4 v[V];
    const float4* ir = (const float4*)(in + (size_t)row * D);
    float s = 0.f;
    #pragma unroll
    for (int i = 0; i < V; i++){
        v[i] = ir[lane + i*32];
        s += v[i].x + v[i].y + v[i].z + v[i].w;
    }
    s = wsum(s);
    float mu = s * (1.0f / D);
    float q = 0.f;
    #pragma unroll
    for (int i = 0; i < V; i++){
        float dx;
        dx = v[i].x - mu; q += dx*dx;
        dx = v[i].y - mu; q += dx*dx;
        dx = v[i].z - mu; q += dx*dx;
        dx = v[i].w - mu; q += dx*dx;
    }
    q = wsum(q);
    float rstd = rsqrtf(q * (1.0f / D) + 1e-5f);
    float4* orow = (float4*)(out + (size_t)row * D);
    #pragma unroll
    for (int i = 0; i < V; i++){
        float4 gg = ((const float4*)g)[lane + i*32];
        float4 bb = ((const float4*)b)[lane + i*32];
        float4 y;
        y.x = (v[i].x - mu) * rstd * gg.x + bb.x;
        y.y = (v[i].y - mu) * rstd * gg.y + bb.y;
        y.z = (v[i].z - mu) * rstd * gg.z + bb.z;
        y.w = (v[i].w - mu) * rstd * gg.w + bb.w;
        orow[lane + i*32] = y;
    }
}

// ---------------- tf32 tensor-core GEMM: C[n,m](fp16) = A[n,k] @ B[k,m] ----------------
#define GBM 128
#define GBN 64
#define GBK 32
#define AS_STRIDE (GBK + 4)
#define BS_STRIDE (GBN + 4)

__global__ void __launch_bounds__(256, 2) gemm_tf32(const float* __restrict__ A,
                                                    const float* __restrict__ B,
                                                    __half* __restrict__ C,
                                                    int n, int k, int m){
    __shared__ float As[GBM][AS_STRIDE];
    __shared__ float Bs[GBK][BS_STRIDE];

    int tid  = threadIdx.x;
    int wid  = tid >> 5;
    int lane = tid & 31;
    int wm   = (wid & 3) * 32;
    int wn   = (wid >> 2) * 32;
    int grp  = lane >> 2;
    int tg   = lane & 3;

    int bm = blockIdx.y * GBM;
    int bn = blockIdx.x * GBN;

    float acc[2][4][4];
    #pragma unroll
    for (int i=0;i<2;i++)
        #pragma unroll
        for (int j=0;j<4;j++)
            #pragma unroll
            for (int l=0;l<4;l++) acc[i][j][l] = 0.f;

    int arow  = tid >> 3;
    int acol  = (tid & 7) * 4;
    int brow  = tid >> 4;
    int bcol  = (tid & 15) * 4;

    for (int k0 = 0; k0 < k; k0 += GBK){
        #pragma unroll
        for (int i = 0; i < 4; i++){
            int row = arow + i*32;
            float4 v = make_float4(0,0,0,0);
            int gr = bm + row;
            if (gr < n) v = *(const float4*)&A[(size_t)gr * k + k0 + acol];
            As[row][acol+0] = __uint_as_float(tf32_of(v.x));
            As[row][acol+1] = __uint_as_float(tf32_of(v.y));
            As[row][acol+2] = __uint_as_float(tf32_of(v.z));
            As[row][acol+3] = __uint_as_float(tf32_of(v.w));
        }
        #pragma unroll
        for (int i = 0; i < 2; i++){
            int row = brow + i*16;
            float4 v = *(const float4*)&B[(size_t)(k0 + row) * m + bn + bcol];
            Bs[row][bcol+0] = __uint_as_float(tf32_of(v.x));
            Bs[row][bcol+1] = __uint_as_float(tf32_of(v.y));
            Bs[row][bcol+2] = __uint_as_float(tf32_of(v.z));
            Bs[row][bcol+3] = __uint_as_float(tf32_of(v.w));
        }
        __syncthreads();

        #pragma unroll
        for (int kk = 0; kk < 4; kk++){
            unsigned a[2][4], bfr[4][2];
            #pragma unroll
            for (int mt = 0; mt < 2; mt++){
                int r = wm + mt*16 + grp;
                int c = kk*8 + tg;
                a[mt][0] = __float_as_uint(As[r    ][c    ]);
                a[mt][1] = __float_as_uint(As[r + 8][c    ]);
                a[mt][2] = __float_as_uint(As[r    ][c + 4]);
                a[mt][3] = __float_as_uint(As[r + 8][c + 4]);
            }
            #pragma unroll
            for (int nt = 0; nt < 4; nt++){
                int c = wn + nt*8 + grp;
                int r = kk*8 + tg;
                bfr[nt][0] = __float_as_uint(Bs[r    ][c]);
                bfr[nt][1] = __float_as_uint(Bs[r + 4][c]);
            }
            #pragma unroll
            for (int mt = 0; mt < 2; mt++)
                #pragma unroll
                for (int nt = 0; nt < 4; nt++){
                    asm volatile(
                        "mma.sync.aligned.m16n8k8.row.col.f32.tf32.tf32.f32 "
                        "{%0,%1,%2,%3}, {%4,%5,%6,%7}, {%8,%9}, {%0,%1,%2,%3};"
                        : "+f"(acc[mt][nt][0]), "+f"(acc[mt][nt][1]),
                          "+f"(acc[mt][nt][2]), "+f"(acc[mt][nt][3])
                        : "r"(a[mt][0]), "r"(a[mt][1]), "r"(a[mt][2]), "r"(a[mt][3]),
                          "r"(bfr[nt][0]), "r"(bfr[nt][1]));
                }
        }
        __syncthreads();
    }

    #pragma unroll
    for (int mt = 0; mt < 2; mt++){
        int r0 = bm + wm + mt*16 + grp;
        int r1 = r0 + 8;
        #pragma unroll
        for (int nt = 0; nt < 4; nt++){
            int c = bn + wn + nt*8 + 2*tg;
            if (r0 < n) *(__half2*)&C[(size_t)r0 * m + c] = __floats2half2_rn(acc[mt][nt][0], acc[mt][nt][1]);
            if (r1 < n) *(__half2*)&C[(size_t)r1 * m + c] = __floats2half2_rn(acc[mt][nt][2], acc[mt][nt][3]);
        }
    }
}

// ------- attention logits H=4: ONE warp per node; 2x uint4 per lane = full 512 halves -------
__global__ void attn_logits4(const __half* __restrict__ xh, const float* __restrict__ as_,
                             const float* __restrict__ ad_, float* __restrict__ als,
                             float* __restrict__ ald){
    int node = (blockIdx.x * blockDim.x + threadIdx.x) >> 5;
    if (node >= Nn) return;
    int lane = threadIdx.x & 31;
    int hd = lane >> 3;       // head 0..3
    int sl = lane & 7;        // slot within head: 8 lanes x 16 ch = 128 ch

    // head hd occupies uint4 indices [hd*16, hd*16+16); this lane takes 2 of them
    const uint4* xr = (const uint4*)(xh + (size_t)node * F1) + hd*16 + sl*2;
    uint4 u0 = xr[0], u1 = xr[1];
    float4 x0 = h4_to_f4(u0.x, u0.y);
    float4 x1 = h4_to_f4(u0.z, u0.w);
    float4 x2 = h4_to_f4(u1.x, u1.y);
    float4 x3 = h4_to_f4(u1.z, u1.w);
    // matching attention slices: channels sl*16 .. sl*16+15 -> float4 indices sl*4 .. sl*4+3
    const float4* svp = (const float4*)(as_ + hd * HIDC) + sl*4;
    const float4* dvp = (const float4*)(ad_ + hd * HIDC) + sl*4;
    float4 s0 = svp[0], s1 = svp[1], s2 = svp[2], s3 = svp[3];
    float4 d0 = dvp[0], d1 = dvp[1], d2 = dvp[2], d3 = dvp[3];
    float s = x0.x*s0.x + x0.y*s0.y + x0.z*s0.z + x0.w*s0.w
            + x1.x*s1.x + x1.y*s1.y + x1.z*s1.z + x1.w*s1.w
            + x2.x*s2.x + x2.y*s2.y + x2.z*s2.z + x2.w*s2.w
            + x3.x*s3.x + x3.y*s3.y + x3.z*s3.z + x3.w*s3.w;
    float d = x0.x*d0.x + x0.y*d0.y + x0.z*d0.z + x0.w*d0.w
            + x1.x*d1.x + x1.y*d1.y + x1.z*d1.z + x1.w*d1.w
            + x2.x*d2.x + x2.y*d2.y + x2.z*d2.z + x2.w*d2.w
            + x3.x*d3.x + x3.y*d3.y + x3.z*d3.z + x3.w*d3.w;
    #pragma unroll
    for (int o = 4; o; o >>= 1){
        s += __shfl_xor_sync(0xffffffffu, s, o);
        d += __shfl_xor_sync(0xffffffffu, d, o);
    }
    if (sl == 0){ als[node*NH1 + hd] = s; ald[node*NH1 + hd] = d; }
}

// ------- attention logits H=1 (fp16 features) -------
__global__ void attn_logits1(const __half* __restrict__ xh, const float* __restrict__ as_,
                             const float* __restrict__ ad_, float* __restrict__ als,
                             float* __restrict__ ald){
    int w = (blockIdx.x * blockDim.x + threadIdx.x) >> 5;
    if (w >= Nn) return;
    int lane = threadIdx.x & 31;
    uint2 u = ((const uint2*)(xh + (size_t)w * HIDC))[lane];
    float4 x = h4_to_f4(u.x, u.y);
    float4 sv = ((const float4*)as_)[lane];
    float4 dv = ((const float4*)ad_)[lane];
    float s = x.x*sv.x + x.y*sv.y + x.z*sv.z + x.w*sv.w;
    float d = x.x*dv.x + x.y*dv.y + x.z*dv.z + x.w*dv.w;
    s = wsum(s); d = wsum(d);
    if (lane == 0){ als[w] = s; ald[w] = d; }
}

// ------ GAT agg H=4: two warps/node, ONE LDG.128 per lane per edge ------
__global__ void __launch_bounds__(256) gat_agg4_fused(const float4* __restrict__ als4,
                                                      const float4* __restrict__ ald4,
                                                      const __half* __restrict__ xh,
                                                      const float* __restrict__ bias,
                                                      const float* __restrict__ gw,
                                                      const float* __restrict__ bw,
                                                      float* __restrict__ h1){
    __shared__ float s_part[8], q_part[8];
    int wib  = threadIdx.x >> 5;
    int node = blockIdx.x * 4 + (wib >> 1);
    int sub  = wib & 1;                     // which head-pair
    int lane = threadIdx.x & 31;
    int hsel = lane >> 4;                   // 0: first head of pair, 1: second

    float4 adv = ald4[node];
    float ad0 = sub ? adv.z : adv.x;
    float ad1 = sub ? adv.w : adv.y;
    int pbeg = g_rowptr[node], pend = g_rowptr[node+1];

    // single pass: lane-local online softmax states for both heads (scalar loads)
    float m0 = -1e30f, d0 = 0.f, m1 = -1e30f, d1 = 0.f;
    for (int p = pbeg + lane; p < pend; p += 32){
        float4 as = als4[g_csr_src[p]];
        float s0 = sub ? as.z : as.x;
        float s1 = sub ? as.w : as.y;
        softmax_push(m0, d0, lrelu(s0 + ad0));
        softmax_push(m1, d1, lrelu(s1 + ad1));
    }
    softmax_merge(m0, d0);
    softmax_merge(m1, d1);
    float r0 = 1.f/d0, r1 = 1.f/d1;
    float mh = hsel ? m1 : m0;              // this lane's head max
    float rh = hsel ? r1 : r0;

    // feature pass: one uint4 per lane per edge (8 halves = this lane's channels)
    float4 aA = make_float4(0,0,0,0), aB = aA;
    #pragma unroll 4
    for (int p = pbeg; p < pend; p++){
        int s = g_csr_src[p];
        float4 as = als4[s];
        float s0 = sub ? as.z : as.x;
        float s1 = sub ? as.w : as.y;
        float v  = hsel ? lrelu(s1 + ad1) : lrelu(s0 + ad0);
        float e  = __expf(v - mh);
        uint4 u = ((const uint4*)(xh + (size_t)s * F1 + sub*256))[lane];
        float4 xA = h4_to_f4(u.x, u.y);
        float4 xB = h4_to_f4(u.z, u.w);
        aA.x += e*xA.x; aA.y += e*xA.y; aA.z += e*xA.z; aA.w += e*xA.w;
        aB.x += e*xB.x; aB.y += e*xB.y; aB.z += e*xB.z; aB.w += e*xB.w;
    }

    // epilogue: bias; LN over 512 (warp + pair reduce); gelu; write
    const float4* b4 = (const float4*)bias + sub*64 + lane*2;
    float4 qA = b4[0], qB = b4[1];
    float4 vA, vB;
    vA.x = aA.x*rh + qA.x; vA.y = aA.y*rh + qA.y; vA.z = aA.z*rh + qA.z; vA.w = aA.w*rh + qA.w;
    vB.x = aB.x*rh + qB.x; vB.y = aB.y*rh + qB.y; vB.z = aB.z*rh + qB.z; vB.w = aB.w*rh + qB.w;

    float ssum = wsum(vA.x+vA.y+vA.z+vA.w + vB.x+vB.y+vB.z+vB.w);
    if (lane == 0) s_part[wib] = ssum;
    __syncthreads();
    int base = wib & ~1;
    float mu = (s_part[base] + s_part[base+1]) * (1.0f / F1);

    float q = 0.f, dx;
    dx=vA.x-mu; q+=dx*dx; dx=vA.y-mu; q+=dx*dx; dx=vA.z-mu; q+=dx*dx; dx=vA.w-mu; q+=dx*dx;
    dx=vB.x-mu; q+=dx*dx; dx=vB.y-mu; q+=dx*dx; dx=vB.z-mu; q+=dx*dx; dx=vB.w-mu; q+=dx*dx;
    q = wsum(q);
    if (lane == 0) q_part[wib] = q;
    __syncthreads();
    float rstd = rsqrtf((q_part[base] + q_part[base+1]) * (1.0f / F1) + 1e-5f);

    const float4* g4 = (const float4*)gw + sub*64 + lane*2;
    const float4* w4 = (const float4*)bw + sub*64 + lane*2;
    float4* orow = (float4*)(h1 + (size_t)node * F1) + sub*64 + lane*2;
    float4 gg = g4[0], bb = w4[0];
    float4 y;
    y.x = gelu_exact((vA.x - mu) * rstd * gg.x + bb.x);
    y.y = gelu_exact((vA.y - mu) * rstd * gg.y + bb.y);
    y.z = gelu_exact((vA.z - mu) * rstd * gg.z + bb.z);
    y.w = gelu_exact((vA.w - mu) * rstd * gg.w + bb.w);
    orow[0] = y;
    gg = g4[1]; bb = w4[1];
    y.x = gelu_exact((vB.x - mu) * rstd * gg.x + bb.x);
    y.y = gelu_exact((vB.y - mu) * rstd * gg.y + bb.y);
    y.z = gelu_exact((vB.z - mu) * rstd * gg.z + bb.z);
    y.w = gelu_exact((vB.w - mu) * rstd * gg.w + bb.w);
    orow[1] = y;
}

// ------- GAT agg H=1 (fp16) + bias + LN + GELU + out-projection + log_softmax -------
__global__ void __launch_bounds__(256) gat_agg1_fused(const float* __restrict__ als,
                                                      const float* __restrict__ ald,
                                                      const __half* __restrict__ xh,
                                                      const float* __restrict__ bias,
                                                      const float* __restrict__ gw,
                                                      const float* __restrict__ bw,
                                                      const float* __restrict__ Wo,
                                                      const float* __restrict__ bo,
                                                      float* __restrict__ out){
    int node = blockIdx.x * (blockDim.x >> 5) + (threadIdx.x >> 5);
    if (node >= Nn) return;
    int lane = threadIdx.x & 31;
    float ad = ald[node];
    int pbeg = g_rowptr[node], pend = g_rowptr[node+1];

    // single pass max+den (lane-local online, exact merge)
    float m = -1e30f, den = 0.f;
    for (int p = pbeg + lane; p < pend; p += 32)
        softmax_push(m, den, lrelu(als[g_csr_src[p]] + ad));
    softmax_merge(m, den);
    float r = 1.f/den;

    float4 acc = make_float4(0,0,0,0);
    #pragma unroll 2
    for (int p = pbeg; p < pend; p++){
        int s = g_csr_src[p];
        float e = __expf(lrelu(als[s] + ad) - m);
        uint2 u = ((const uint2*)(xh + (size_t)s * HIDC))[lane];
        float4 xv = h4_to_f4(u.x, u.y);
        acc.x += e*xv.x; acc.y += e*xv.y; acc.z += e*xv.z; acc.w += e*xv.w;
    }

    float4 qb = ((const float4*)bias)[lane];
    float4 v;
    v.x = acc.x*r + qb.x; v.y = acc.y*r + qb.y; v.z = acc.z*r + qb.z; v.w = acc.w*r + qb.w;
    float s = wsum(v.x + v.y + v.z + v.w);
    float mu = s * (1.0f / HIDC);
    float q = 0.f, dx;
    dx=v.x-mu; q+=dx*dx; dx=v.y-mu; q+=dx*dx; dx=v.z-mu; q+=dx*dx; dx=v.w-mu; q+=dx*dx;
    q = wsum(q);
    float rstd = rsqrtf(q * (1.0f / HIDC) + 1e-5f);
    float4 gg = ((const float4*)gw)[lane];
    float4 bb = ((const float4*)bw)[lane];
    float4 y;
    y.x = gelu_exact((v.x - mu) * rstd * gg.x + bb.x);
    y.y = gelu_exact((v.y - mu) * rstd * gg.y + bb.y);
    y.z = gelu_exact((v.z - mu) * rstd * gg.z + bb.z);
    y.w = gelu_exact((v.w - mu) * rstd * gg.w + bb.w);

    // fused output projection
    float z = bo[lane];
    #pragma unroll 8
    for (int k4 = 0; k4 < 32; k4++){
        float yx = __shfl_sync(0xffffffffu, y.x, k4);
        float yy = __shfl_sync(0xffffffffu, y.y, k4);
        float yz = __shfl_sync(0xffffffffu, y.z, k4);
        float yw = __shfl_sync(0xffffffffu, y.w, k4);
        const float* wr = Wo + k4*4*DOUT + lane;
        z += yx*wr[0] + yy*wr[DOUT] + yz*wr[2*DOUT] + yw*wr[3*DOUT];
    }
    float mx = wmax(z);
    float ex = expf(z - mx);
    float sm = wsum(ex);
    out[(size_t)node * DOUT + lane] = z - mx - logf(sm);
}

// ---------------- launch ----------------
extern "C" void kernel_launch(void* const* d_in, const int* in_sizes, int n_in,
                              void* d_out, int out_size){
    const float* x      = (const float*)d_in[0];
    const void*  ei     = d_in[1];
    const float* g_in   = (const float*)d_in[2];
    const float* b_in   = (const float*)d_in[3];
    const float* W1     = (const float*)d_in[4];
    const float* att1_s = (const float*)d_in[5];
    const float* att1_d = (const float*)d_in[6];
    const float* bias1  = (const float*)d_in[7];
    const float* g1     = (const float*)d_in[8];
    const float* b1     = (const float*)d_in[9];
    const float* W2     = (const float*)d_in[10];
    const float* att2_s = (const float*)d_in[11];
    const float* att2_d = (const float*)d_in[12];
    const float* bias2  = (const float*)d_in[13];
    const float* g2     = (const float*)d_in[14];
    const float* b2     = (const float*)d_in[15];
    const float* Wo     = (const float*)d_in[16];
    const float* bo     = (const float*)d_in[17];
    float* out = (float*)d_out;

    void *p_h0, *p_xh1, *p_al1s, *p_al1d, *p_h1;
    void *p_xh2, *p_al2s, *p_al2d, *p_is32, *p_deg;
    cudaGetSymbolAddress(&p_h0,   g_h0);
    cudaGetSymbolAddress(&p_xh1,  g_xh1);
    cudaGetSymbolAddress(&p_al1s, g_al1s);
    cudaGetSymbolAddress(&p_al1d, g_al1d);
    cudaGetSymbolAddress(&p_h1,   g_h1);
    cudaGetSymbolAddress(&p_xh2,  g_xh2);
    cudaGetSymbolAddress(&p_al2s, g_al2s);
    cudaGetSymbolAddress(&p_al2d, g_al2d);
    cudaGetSymbolAddress(&p_is32, g_is32);
    cudaGetSymbolAddress(&p_deg,  g_deg);

    const int T = 256;
    const int warpsPB = T / 32;

    // ---- side stream for CSR build (fork/join via events; capture-legal) ----
    cudaStream_t s2;
    cudaStreamCreate(&s2);
    cudaEvent_t evF, evJ;
    cudaEventCreateWithFlags(&evF, cudaEventDisableTiming);
    cudaEventCreateWithFlags(&evJ, cudaEventDisableTiming);

    cudaEventRecord(evF, 0);
    cudaStreamWaitEvent(s2, evF, 0);

    cudaMemsetAsync(p_is32, 0, sizeof(int), s2);
    cudaMemsetAsync(p_deg,  0, Nn * sizeof(int), s2);
    detect_dtype<<<16, 256, 0, s2>>>((const long long*)ei);
    decode_edges<<<(ETOT + T - 1)/T, T, 0, s2>>>((const int*)ei);
    scan_tiles<<<NTILES, 256, 0, s2>>>();
    scan_sums<<<1, 128, 0, s2>>>();
    scan_finalize<<<NTILES, 256, 0, s2>>>();
    build_csr<<<(ETOT + T - 1)/T, T, 0, s2>>>();
    cudaEventRecord(evJ, s2);

    // ---- dense path on main stream ----
    ln_kernel<128><<<(Nn + warpsPB - 1)/warpsPB, T>>>(x, g_in, b_in, (float*)p_h0);
    {
        dim3 grid(F1/GBN, (Nn + GBM - 1)/GBM);
        gemm_tf32<<<grid, 256>>>((const float*)p_h0, W1, (__half*)p_xh1, Nn, DIN, F1);
    }
    attn_logits4<<<(Nn + warpsPB - 1)/warpsPB, T>>>((const __half*)p_xh1, att1_s, att1_d,
                                                    (float*)p_al1s, (float*)p_al1d);

    // join CSR before aggregation
    cudaStreamWaitEvent(0, evJ, 0);

    gat_agg4_fused<<<Nn/4, T>>>((const float4*)p_al1s, (const float4*)p_al1d,
                                (const __half*)p_xh1, bias1, g1, b1, (float*)p_h1);

    {
        dim3 grid(HIDC/GBN, (Nn + GBM - 1)/GBM);
        gemm_tf32<<<grid, 256>>>((const float*)p_h1, W2, (__half*)p_xh2, Nn, F1, HIDC);
    }
    attn_logits1<<<(Nn + warpsPB - 1)/warpsPB, T>>>((const __half*)p_xh2, att2_s, att2_d,
                                                    (float*)p_al2s, (float*)p_al2d);
    gat_agg1_fused<<<(Nn + warpsPB - 1)/warpsPB, T>>>((const float*)p_al2s, (const float*)p_al2d,
                                                      (const __half*)p_xh2, bias2, g2, b2,
                                                      Wo, bo, out);
}

// round 15
// speedup vs baseline: 1.5025x; 1.0213x over previous
#include <cuda_runtime.h>
#include <cuda_fp16.h>
#include <math.h>
#include <limits.h>

#define Nn    20000
#define Ee    320000
#define ETOT  340000   // Ee + Nn self loops
#define DIN   128
#define HIDC  128
#define NH1   4
#define F1    512      // NH1*HIDC
#define DOUT  32
#define NTILES ((Nn + 255) / 256)   // 79
#define ECAP  128                   // per-warp smem edge cache (max in-degree ~45)

// ---------------- scratch (device globals; allocation-free) ----------------
__device__ __align__(16) float  g_h0  [Nn*DIN];
__device__ __align__(16) __half g_xh1 [(size_t)Nn*F1];
__device__ __align__(16) float  g_al1s[Nn*NH1];
__device__ __align__(16) float  g_al1d[Nn*NH1];
__device__ __align__(16) float  g_h1  [(size_t)Nn*F1];
__device__ __align__(16) __half g_xh2 [Nn*HIDC];
__device__              float   g_al2s[Nn];
__device__              float   g_al2d[Nn];
__device__              int     g_src [ETOT];
__device__              int     g_dst [ETOT];
__device__              int     g_deg [Nn];
__device__              int     g_scantmp[Nn];
__device__              int     g_tilesum[128];
__device__              int     g_tileoff[128];
__device__              int     g_rowptr[Nn+1];
__device__              int     g_cursor[Nn];
__device__              int     g_csr_src[ETOT];
__device__              int     g_is32;

// ---------------- helpers ----------------
__device__ __forceinline__ float wsum(float v){
    #pragma unroll
    for (int o = 16; o; o >>= 1) v += __shfl_xor_sync(0xffffffffu, v, o);
    return v;
}
__device__ __forceinline__ float wmax(float v){
    #pragma unroll
    for (int o = 16; o; o >>= 1) v = fmaxf(v, __shfl_xor_sync(0xffffffffu, v, o));
    return v;
}
__device__ __forceinline__ float gelu_exact(float x){
    return 0.5f * x * (1.0f + erff(x * 0.70710678118654752f));
}
__device__ __forceinline__ unsigned tf32_of(float x){
    unsigned u; asm("cvt.rna.tf32.f32 %0, %1;" : "=r"(u) : "f"(x)); return u;
}
__device__ __forceinline__ float lrelu(float x){ return x > 0.f ? x : 0.2f * x; }

__device__ __forceinline__ float4 h4_to_f4(unsigned lo, unsigned hi){
    __half2 l = *reinterpret_cast<__half2*>(&lo);
    __half2 h = *reinterpret_cast<__half2*>(&hi);
    float2 a = __half22float2(l), b = __half22float2(h);
    return make_float4(a.x, a.y, b.x, b.y);
}

// exact warp-wide merge of per-lane (max, expsum) softmax states
__device__ __forceinline__ void softmax_merge(float& m, float& d){
    #pragma unroll
    for (int o = 16; o; o >>= 1){
        float om = __shfl_xor_sync(0xffffffffu, m, o);
        float od = __shfl_xor_sync(0xffffffffu, d, o);
        float nm = fmaxf(m, om);
        d = d*__expf(m - nm) + od*__expf(om - nm);
        m = nm;
    }
}
// lane-local online accumulate of value v into (m, d)
__device__ __forceinline__ void softmax_push(float& m, float& d, float v){
    float nm = fmaxf(m, v);
    d = d*__expf(m - nm) + __expf(v - nm);
    m = nm;
}

// ---------------- edge dtype detection + decode (+degree count) ----------------
__global__ void detect_dtype(const long long* __restrict__ p){
    long long stride = (2LL * Ee) / 4096;
    if (stride < 1) stride = 1;
    long long idx = (long long)(blockIdx.x * blockDim.x + threadIdx.x) * stride;
    if (idx >= 2LL * Ee) return;
    long long v = p[idx];
    if (v < 0 || v >= Nn) atomicExch(&g_is32, 1);
}

__global__ void decode_edges(const int* __restrict__ p32){
    int e = blockIdx.x * blockDim.x + threadIdx.x;
    if (e >= ETOT) return;
    int s, d;
    if (e < Ee){
        if (g_is32){ s = p32[e];   d = p32[Ee + e]; }
        else       { s = p32[2*e]; d = p32[2*Ee + 2*e]; }
    } else {
        s = d = e - Ee;
    }
    g_src[e] = s; g_dst[e] = d;
    atomicAdd(&g_deg[d], 1);
}

// ---------------- parallel 3-kernel scan of g_deg -> g_rowptr ----------------
__global__ void scan_tiles(){
    __shared__ int sh[256];
    int i = blockIdx.x * 256 + threadIdx.x;
    int v = (i < Nn) ? g_deg[i] : 0;
    sh[threadIdx.x] = v;
    __syncthreads();
    for (int off = 1; off < 256; off <<= 1){
        int t = (threadIdx.x >= off) ? sh[threadIdx.x - off] : 0;
        __syncthreads();
        sh[threadIdx.x] += t;
        __syncthreads();
    }
    if (i < Nn) g_scantmp[i] = sh[threadIdx.x];
    if (threadIdx.x == 255) g_tilesum[blockIdx.x] = sh[255];
}

__global__ void scan_sums(){
    __shared__ int sh[128];
    int t = threadIdx.x;
    sh[t] = (t < NTILES) ? g_tilesum[t] : 0;
    __syncthreads();
    for (int off = 1; off < 128; off <<= 1){
        int v = (t >= off) ? sh[t - off] : 0;
        __syncthreads();
        sh[t] += v;
        __syncthreads();
    }
    if (t < NTILES) g_tileoff[t] = (t == 0) ? 0 : sh[t - 1];
}

__global__ void scan_finalize(){
    int i = blockIdx.x * 256 + threadIdx.x;
    if (i >= Nn) return;
    int r = g_scantmp[i] - g_deg[i] + g_tileoff[i >> 8];
    g_rowptr[i] = r;
    g_cursor[i] = r;
    if (i == 0) g_rowptr[Nn] = ETOT;
}

__global__ void build_csr(){
    int e = blockIdx.x * blockDim.x + threadIdx.x;
    if (e >= ETOT) return;
    int pos = atomicAdd(&g_cursor[g_dst[e]], 1);
    g_csr_src[pos] = g_src[e];
}

// ---------------- standalone LayerNorm (input only) ----------------
template<int D>
__global__ void ln_kernel(const float* __restrict__ in, const float* __restrict__ g,
                          const float* __restrict__ b, float* __restrict__ out){
    int row = blockIdx.x * (blockDim.x >> 5) + (threadIdx.x >> 5);
    if (row >= Nn) return;
    int lane = threadIdx.x & 31;
    constexpr int V = D / 128;
    float4 v[V];
    const float4* ir = (const float4*)(in + (size_t)row * D);
    float s = 0.f;
    #pragma unroll
    for (int i = 0; i < V; i++){
        v[i] = ir[lane + i*32];
        s += v[i].x + v[i].y + v[i].z + v[i].w;
    }
    s = wsum(s);
    float mu = s * (1.0f / D);
    float q = 0.f;
    #pragma unroll
    for (int i = 0; i < V; i++){
        float dx;
        dx = v[i].x - mu; q += dx*dx;
        dx = v[i].y - mu; q += dx*dx;
        dx = v[i].z - mu; q += dx*dx;
        dx = v[i].w - mu; q += dx*dx;
    }
    q = wsum(q);
    float rstd = rsqrtf(q * (1.0f / D) + 1e-5f);
    float4* orow = (float4*)(out + (size_t)row * D);
    #pragma unroll
    for (int i = 0; i < V; i++){
        float4 gg = ((const float4*)g)[lane + i*32];
        float4 bb = ((const float4*)b)[lane + i*32];
        float4 y;
        y.x = (v[i].x - mu) * rstd * gg.x + bb.x;
        y.y = (v[i].y - mu) * rstd * gg.y + bb.y;
        y.z = (v[i].z - mu) * rstd * gg.z + bb.z;
        y.w = (v[i].w - mu) * rstd * gg.w + bb.w;
        orow[lane + i*32] = y;
    }
}

// ---------------- tf32 tensor-core GEMM: C[n,m](fp16) = A[n,k] @ B[k,m] ----------------
#define GBM 128
#define GBN 64
#define GBK 32
#define AS_STRIDE (GBK + 4)
#define BS_STRIDE (GBN + 4)

__global__ void __launch_bounds__(256, 2) gemm_tf32(const float* __restrict__ A,
                                                    const float* __restrict__ B,
                                                    __half* __restrict__ C,
                                                    int n, int k, int m){
    __shared__ float As[GBM][AS_STRIDE];
    __shared__ float Bs[GBK][BS_STRIDE];

    int tid  = threadIdx.x;
    int wid  = tid >> 5;
    int lane = tid & 31;
    int wm   = (wid & 3) * 32;
    int wn   = (wid >> 2) * 32;
    int grp  = lane >> 2;
    int tg   = lane & 3;

    int bm = blockIdx.y * GBM;
    int bn = blockIdx.x * GBN;

    float acc[2][4][4];
    #pragma unroll
    for (int i=0;i<2;i++)
        #pragma unroll
        for (int j=0;j<4;j++)
            #pragma unroll
            for (int l=0;l<4;l++) acc[i][j][l] = 0.f;

    int arow  = tid >> 3;
    int acol  = (tid & 7) * 4;
    int brow  = tid >> 4;
    int bcol  = (tid & 15) * 4;

    for (int k0 = 0; k0 < k; k0 += GBK){
        #pragma unroll
        for (int i = 0; i < 4; i++){
            int row = arow + i*32;
            float4 v = make_float4(0,0,0,0);
            int gr = bm + row;
            if (gr < n) v = *(const float4*)&A[(size_t)gr * k + k0 + acol];
            As[row][acol+0] = __uint_as_float(tf32_of(v.x));
            As[row][acol+1] = __uint_as_float(tf32_of(v.y));
            As[row][acol+2] = __uint_as_float(tf32_of(v.z));
            As[row][acol+3] = __uint_as_float(tf32_of(v.w));
        }
        #pragma unroll
        for (int i = 0; i < 2; i++){
            int row = brow + i*16;
            float4 v = *(const float4*)&B[(size_t)(k0 + row) * m + bn + bcol];
            Bs[row][bcol+0] = __uint_as_float(tf32_of(v.x));
            Bs[row][bcol+1] = __uint_as_float(tf32_of(v.y));
            Bs[row][bcol+2] = __uint_as_float(tf32_of(v.z));
            Bs[row][bcol+3] = __uint_as_float(tf32_of(v.w));
        }
        __syncthreads();

        #pragma unroll
        for (int kk = 0; kk < 4; kk++){
            unsigned a[2][4], bfr[4][2];
            #pragma unroll
            for (int mt = 0; mt < 2; mt++){
                int r = wm + mt*16 + grp;
                int c = kk*8 + tg;
                a[mt][0] = __float_as_uint(As[r    ][c    ]);
                a[mt][1] = __float_as_uint(As[r + 8][c    ]);
                a[mt][2] = __float_as_uint(As[r    ][c + 4]);
                a[mt][3] = __float_as_uint(As[r + 8][c + 4]);
            }
            #pragma unroll
            for (int nt = 0; nt < 4; nt++){
                int c = wn + nt*8 + grp;
                int r = kk*8 + tg;
                bfr[nt][0] = __float_as_uint(Bs[r    ][c]);
                bfr[nt][1] = __float_as_uint(Bs[r + 4][c]);
            }
            #pragma unroll
            for (int mt = 0; mt < 2; mt++)
                #pragma unroll
                for (int nt = 0; nt < 4; nt++){
                    asm volatile(
                        "mma.sync.aligned.m16n8k8.row.col.f32.tf32.tf32.f32 "
                        "{%0,%1,%2,%3}, {%4,%5,%6,%7}, {%8,%9}, {%0,%1,%2,%3};"
                        : "+f"(acc[mt][nt][0]), "+f"(acc[mt][nt][1]),
                          "+f"(acc[mt][nt][2]), "+f"(acc[mt][nt][3])
                        : "r"(a[mt][0]), "r"(a[mt][1]), "r"(a[mt][2]), "r"(a[mt][3]),
                          "r"(bfr[nt][0]), "r"(bfr[nt][1]));
                }
        }
        __syncthreads();
    }

    #pragma unroll
    for (int mt = 0; mt < 2; mt++){
        int r0 = bm + wm + mt*16 + grp;
        int r1 = r0 + 8;
        #pragma unroll
        for (int nt = 0; nt < 4; nt++){
            int c = bn + wn + nt*8 + 2*tg;
            if (r0 < n) *(__half2*)&C[(size_t)r0 * m + c] = __floats2half2_rn(acc[mt][nt][0], acc[mt][nt][1]);
            if (r1 < n) *(__half2*)&C[(size_t)r1 * m + c] = __floats2half2_rn(acc[mt][nt][2], acc[mt][nt][3]);
        }
    }
}

// ------- attention logits H=4: ONE warp per node; 2x uint4 per lane = full 512 halves -------
__global__ void attn_logits4(const __half* __restrict__ xh, const float* __restrict__ as_,
                             const float* __restrict__ ad_, float* __restrict__ als,
                             float* __restrict__ ald){
    int node = (blockIdx.x * blockDim.x + threadIdx.x) >> 5;
    if (node >= Nn) return;
    int lane = threadIdx.x & 31;
    int hd = lane >> 3;
    int sl = lane & 7;

    const uint4* xr = (const uint4*)(xh + (size_t)node * F1) + hd*16 + sl*2;
    uint4 u0 = xr[0], u1 = xr[1];
    float4 x0 = h4_to_f4(u0.x, u0.y);
    float4 x1 = h4_to_f4(u0.z, u0.w);
    float4 x2 = h4_to_f4(u1.x, u1.y);
    float4 x3 = h4_to_f4(u1.z, u1.w);
    const float4* svp = (const float4*)(as_ + hd * HIDC) + sl*4;
    const float4* dvp = (const float4*)(ad_ + hd * HIDC) + sl*4;
    float4 s0 = svp[0], s1 = svp[1], s2 = svp[2], s3 = svp[3];
    float4 d0 = dvp[0], d1 = dvp[1], d2 = dvp[2], d3 = dvp[3];
    float s = x0.x*s0.x + x0.y*s0.y + x0.z*s0.z + x0.w*s0.w
            + x1.x*s1.x + x1.y*s1.y + x1.z*s1.z + x1.w*s1.w
            + x2.x*s2.x + x2.y*s2.y + x2.z*s2.z + x2.w*s2.w
            + x3.x*s3.x + x3.y*s3.y + x3.z*s3.z + x3.w*s3.w;
    float d = x0.x*d0.x + x0.y*d0.y + x0.z*d0.z + x0.w*d0.w
            + x1.x*d1.x + x1.y*d1.y + x1.z*d1.z + x1.w*d1.w
            + x2.x*d2.x + x2.y*d2.y + x2.z*d2.z + x2.w*d2.w
            + x3.x*d3.x + x3.y*d3.y + x3.z*d3.z + x3.w*d3.w;
    #pragma unroll
    for (int o = 4; o; o >>= 1){
        s += __shfl_xor_sync(0xffffffffu, s, o);
        d += __shfl_xor_sync(0xffffffffu, d, o);
    }
    if (sl == 0){ als[node*NH1 + hd] = s; ald[node*NH1 + hd] = d; }
}

// ------- attention logits H=1 (fp16 features) -------
__global__ void attn_logits1(const __half* __restrict__ xh, const float* __restrict__ as_,
                             const float* __restrict__ ad_, float* __restrict__ als,
                             float* __restrict__ ald){
    int w = (blockIdx.x * blockDim.x + threadIdx.x) >> 5;
    if (w >= Nn) return;
    int lane = threadIdx.x & 31;
    uint2 u = ((const uint2*)(xh + (size_t)w * HIDC))[lane];
    float4 x = h4_to_f4(u.x, u.y);
    float4 sv = ((const float4*)as_)[lane];
    float4 dv = ((const float4*)ad_)[lane];
    float s = x.x*sv.x + x.y*sv.y + x.z*sv.z + x.w*sv.w;
    float d = x.x*dv.x + x.y*dv.y + x.z*dv.z + x.w*dv.w;
    s = wsum(s); d = wsum(d);
    if (lane == 0){ als[w] = s; ald[w] = d; }
}

// ------ GAT agg H=4: two warps/node; smem-cached edge logits break the gather chain ------
__global__ void __launch_bounds__(256) gat_agg4_fused(const float4* __restrict__ als4,
                                                      const float4* __restrict__ ald4,
                                                      const __half* __restrict__ xh,
                                                      const float* __restrict__ bias,
                                                      const float* __restrict__ gw,
                                                      const float* __restrict__ bw,
                                                      float* __restrict__ h1){
    __shared__ float  s_part[8], q_part[8];
    __shared__ int    sh_idx[8][ECAP];
    __shared__ float2 sh_v  [8][ECAP];
    int wib  = threadIdx.x >> 5;
    int node = blockIdx.x * 4 + (wib >> 1);
    int sub  = wib & 1;
    int lane = threadIdx.x & 31;
    int hsel = lane >> 4;

    float4 adv = ald4[node];
    float ad0 = sub ? adv.z : adv.x;
    float ad1 = sub ? adv.w : adv.y;
    int pbeg = g_rowptr[node], pend = g_rowptr[node+1];
    int deg  = pend - pbeg;
    int cached = deg < ECAP ? deg : ECAP;

    // softmax pass: gather logits once; cache (idx, v0, v1) in smem
    float m0 = -1e30f, d0 = 0.f, m1 = -1e30f, d1 = 0.f;
    for (int i = lane; i < deg; i += 32){
        int s = g_csr_src[pbeg + i];
        float4 as = als4[s];
        float v0 = lrelu((sub ? as.z : as.x) + ad0);
        float v1 = lrelu((sub ? as.w : as.y) + ad1);
        softmax_push(m0, d0, v0);
        softmax_push(m1, d1, v1);
        if (i < ECAP){ sh_idx[wib][i] = s; sh_v[wib][i] = make_float2(v0, v1); }
    }
    softmax_merge(m0, d0);
    softmax_merge(m1, d1);
    float r0 = 1.f/d0, r1 = 1.f/d1;
    float mh = hsel ? m1 : m0;
    float rh = hsel ? r1 : r0;
    __syncwarp();

    // feature pass: smem logit + one independent LDG.128 per lane per edge
    float4 aA = make_float4(0,0,0,0), aB = aA;
    #pragma unroll 4
    for (int i = 0; i < cached; i++){
        int s = sh_idx[wib][i];
        float2 vv = sh_v[wib][i];
        float e = __expf((hsel ? vv.y : vv.x) - mh);
        uint4 u = ((const uint4*)(xh + (size_t)s * F1 + sub*256))[lane];
        float4 xA = h4_to_f4(u.x, u.y);
        float4 xB = h4_to_f4(u.z, u.w);
        aA.x += e*xA.x; aA.y += e*xA.y; aA.z += e*xA.z; aA.w += e*xA.w;
        aB.x += e*xB.x; aB.y += e*xB.y; aB.z += e*xB.z; aB.w += e*xB.w;
    }
    // tail (deg > ECAP): original global path — practically never taken
    for (int p = pbeg + cached; p < pend; p++){
        int s = g_csr_src[p];
        float4 as = als4[s];
        float v = hsel ? lrelu((sub ? as.w : as.y) + ad1) : lrelu((sub ? as.z : as.x) + ad0);
        float e = __expf(v - mh);
        uint4 u = ((const uint4*)(xh + (size_t)s * F1 + sub*256))[lane];
        float4 xA = h4_to_f4(u.x, u.y);
        float4 xB = h4_to_f4(u.z, u.w);
        aA.x += e*xA.x; aA.y += e*xA.y; aA.z += e*xA.z; aA.w += e*xA.w;
        aB.x += e*xB.x; aB.y += e*xB.y; aB.z += e*xB.z; aB.w += e*xB.w;
    }

    // epilogue: bias; LN over 512 (warp + pair reduce); gelu; write
    const float4* b4 = (const float4*)bias + sub*64 + lane*2;
    float4 qA = b4[0], qB = b4[1];
    float4 vA, vB;
    vA.x = aA.x*rh + qA.x; vA.y = aA.y*rh + qA.y; vA.z = aA.z*rh + qA.z; vA.w = aA.w*rh + qA.w;
    vB.x = aB.x*rh + qB.x; vB.y = aB.y*rh + qB.y; vB.z = aB.z*rh + qB.z; vB.w = aB.w*rh + qB.w;

    float ssum = wsum(vA.x+vA.y+vA.z+vA.w + vB.x+vB.y+vB.z+vB.w);
    if (lane == 0) s_part[wib] = ssum;
    __syncthreads();
    int base = wib & ~1;
    float mu = (s_part[base] + s_part[base+1]) * (1.0f / F1);

    float q = 0.f, dx;
    dx=vA.x-mu; q+=dx*dx; dx=vA.y-mu; q+=dx*dx; dx=vA.z-mu; q+=dx*dx; dx=vA.w-mu; q+=dx*dx;
    dx=vB.x-mu; q+=dx*dx; dx=vB.y-mu; q+=dx*dx; dx=vB.z-mu; q+=dx*dx; dx=vB.w-mu; q+=dx*dx;
    q = wsum(q);
    if (lane == 0) q_part[wib] = q;
    __syncthreads();
    float rstd = rsqrtf((q_part[base] + q_part[base+1]) * (1.0f / F1) + 1e-5f);

    const float4* g4 = (const float4*)gw + sub*64 + lane*2;
    const float4* w4 = (const float4*)bw + sub*64 + lane*2;
    float4* orow = (float4*)(h1 + (size_t)node * F1) + sub*64 + lane*2;
    float4 gg = g4[0], bb = w4[0];
    float4 y;
    y.x = gelu_exact((vA.x - mu) * rstd * gg.x + bb.x);
    y.y = gelu_exact((vA.y - mu) * rstd * gg.y + bb.y);
    y.z = gelu_exact((vA.z - mu) * rstd * gg.z + bb.z);
    y.w = gelu_exact((vA.w - mu) * rstd * gg.w + bb.w);
    orow[0] = y;
    gg = g4[1]; bb = w4[1];
    y.x = gelu_exact((vB.x - mu) * rstd * gg.x + bb.x);
    y.y = gelu_exact((vB.y - mu) * rstd * gg.y + bb.y);
    y.z = gelu_exact((vB.z - mu) * rstd * gg.z + bb.z);
    y.w = gelu_exact((vB.w - mu) * rstd * gg.w + bb.w);
    orow[1] = y;
}

// ------- GAT agg H=1: smem-cached logits + bias+LN+GELU+out_proj+log_softmax -------
__global__ void __launch_bounds__(256) gat_agg1_fused(const float* __restrict__ als,
                                                      const float* __restrict__ ald,
                                                      const __half* __restrict__ xh,
                                                      const float* __restrict__ bias,
                                                      const float* __restrict__ gw,
                                                      const float* __restrict__ bw,
                                                      const float* __restrict__ Wo,
                                                      const float* __restrict__ bo,
                                                      float* __restrict__ out){
    __shared__ int   sh_idx[8][ECAP];
    __shared__ float sh_v  [8][ECAP];
    int wib  = threadIdx.x >> 5;
    int node = blockIdx.x * 8 + wib;
    if (node >= Nn) return;
    int lane = threadIdx.x & 31;
    float ad = ald[node];
    int pbeg = g_rowptr[node], pend = g_rowptr[node+1];
    int deg  = pend - pbeg;
    int cached = deg < ECAP ? deg : ECAP;

    float m = -1e30f, den = 0.f;
    for (int i = lane; i < deg; i += 32){
        int s = g_csr_src[pbeg + i];
        float v = lrelu(als[s] + ad);
        softmax_push(m, den, v);
        if (i < ECAP){ sh_idx[wib][i] = s; sh_v[wib][i] = v; }
    }
    softmax_merge(m, den);
    float r = 1.f/den;
    __syncwarp();

    float4 acc = make_float4(0,0,0,0);
    #pragma unroll 4
    for (int i = 0; i < cached; i++){
        int s = sh_idx[wib][i];
        float e = __expf(sh_v[wib][i] - m);
        uint2 u = ((const uint2*)(xh + (size_t)s * HIDC))[lane];
        float4 xv = h4_to_f4(u.x, u.y);
        acc.x += e*xv.x; acc.y += e*xv.y; acc.z += e*xv.z; acc.w += e*xv.w;
    }
    for (int p = pbeg + cached; p < pend; p++){
        int s = g_csr_src[p];
        float e = __expf(lrelu(als[s] + ad) - m);
        uint2 u = ((const uint2*)(xh + (size_t)s * HIDC))[lane];
        float4 xv = h4_to_f4(u.x, u.y);
        acc.x += e*xv.x; acc.y += e*xv.y; acc.z += e*xv.z; acc.w += e*xv.w;
    }

    float4 qb = ((const float4*)bias)[lane];
    float4 v;
    v.x = acc.x*r + qb.x; v.y = acc.y*r + qb.y; v.z = acc.z*r + qb.z; v.w = acc.w*r + qb.w;
    float s = wsum(v.x + v.y + v.z + v.w);
    float mu = s * (1.0f / HIDC);
    float q = 0.f, dx;
    dx=v.x-mu; q+=dx*dx; dx=v.y-mu; q+=dx*dx; dx=v.z-mu; q+=dx*dx; dx=v.w-mu; q+=dx*dx;
    q = wsum(q);
    float rstd = rsqrtf(q * (1.0f / HIDC) + 1e-5f);
    float4 gg = ((const float4*)gw)[lane];
    float4 bb = ((const float4*)bw)[lane];
    float4 y;
    y.x = gelu_exact((v.x - mu) * rstd * gg.x + bb.x);
    y.y = gelu_exact((v.y - mu) * rstd * gg.y + bb.y);
    y.z = gelu_exact((v.z - mu) * rstd * gg.z + bb.z);
    y.w = gelu_exact((v.w - mu) * rstd * gg.w + bb.w);

    // fused output projection
    float z = bo[lane];
    #pragma unroll 8
    for (int k4 = 0; k4 < 32; k4++){
        float yx = __shfl_sync(0xffffffffu, y.x, k4);
        float yy = __shfl_sync(0xffffffffu, y.y, k4);
        float yz = __shfl_sync(0xffffffffu, y.z, k4);
        float yw = __shfl_sync(0xffffffffu, y.w, k4);
        const float* wr = Wo + k4*4*DOUT + lane;
        z += yx*wr[0] + yy*wr[DOUT] + yz*wr[2*DOUT] + yw*wr[3*DOUT];
    }
    float mx = wmax(z);
    float ex = expf(z - mx);
    float sm = wsum(ex);
    out[(size_t)node * DOUT + lane] = z - mx - logf(sm);
}

// ---------------- launch ----------------
extern "C" void kernel_launch(void* const* d_in, const int* in_sizes, int n_in,
                              void* d_out, int out_size){
    const float* x      = (const float*)d_in[0];
    const void*  ei     = d_in[1];
    const float* g_in   = (const float*)d_in[2];
    const float* b_in   = (const float*)d_in[3];
    const float* W1     = (const float*)d_in[4];
    const float* att1_s = (const float*)d_in[5];
    const float* att1_d = (const float*)d_in[6];
    const float* bias1  = (const float*)d_in[7];
    const float* g1     = (const float*)d_in[8];
    const float* b1     = (const float*)d_in[9];
    const float* W2     = (const float*)d_in[10];
    const float* att2_s = (const float*)d_in[11];
    const float* att2_d = (const float*)d_in[12];
    const float* bias2  = (const float*)d_in[13];
    const float* g2     = (const float*)d_in[14];
    const float* b2     = (const float*)d_in[15];
    const float* Wo     = (const float*)d_in[16];
    const float* bo     = (const float*)d_in[17];
    float* out = (float*)d_out;

    void *p_h0, *p_xh1, *p_al1s, *p_al1d, *p_h1;
    void *p_xh2, *p_al2s, *p_al2d, *p_is32, *p_deg;
    cudaGetSymbolAddress(&p_h0,   g_h0);
    cudaGetSymbolAddress(&p_xh1,  g_xh1);
    cudaGetSymbolAddress(&p_al1s, g_al1s);
    cudaGetSymbolAddress(&p_al1d, g_al1d);
    cudaGetSymbolAddress(&p_h1,   g_h1);
    cudaGetSymbolAddress(&p_xh2,  g_xh2);
    cudaGetSymbolAddress(&p_al2s, g_al2s);
    cudaGetSymbolAddress(&p_al2d, g_al2d);
    cudaGetSymbolAddress(&p_is32, g_is32);
    cudaGetSymbolAddress(&p_deg,  g_deg);

    const int T = 256;
    const int warpsPB = T / 32;

    // ---- side stream for CSR build (fork/join via events; capture-legal) ----
    cudaStream_t s2;
    cudaStreamCreate(&s2);
    cudaEvent_t evF, evJ;
    cudaEventCreateWithFlags(&evF, cudaEventDisableTiming);
    cudaEventCreateWithFlags(&evJ, cudaEventDisableTiming);

    cudaEventRecord(evF, 0);
    cudaStreamWaitEvent(s2, evF, 0);

    cudaMemsetAsync(p_is32, 0, sizeof(int), s2);
    cudaMemsetAsync(p_deg,  0, Nn * sizeof(int), s2);
    detect_dtype<<<16, 256, 0, s2>>>((const long long*)ei);
    decode_edges<<<(ETOT + T - 1)/T, T, 0, s2>>>((const int*)ei);
    scan_tiles<<<NTILES, 256, 0, s2>>>();
    scan_sums<<<1, 128, 0, s2>>>();
    scan_finalize<<<NTILES, 256, 0, s2>>>();
    build_csr<<<(ETOT + T - 1)/T, T, 0, s2>>>();
    cudaEventRecord(evJ, s2);

    // ---- dense path on main stream ----
    ln_kernel<128><<<(Nn + warpsPB - 1)/warpsPB, T>>>(x, g_in, b_in, (float*)p_h0);
    {
        dim3 grid(F1/GBN, (Nn + GBM - 1)/GBM);
        gemm_tf32<<<grid, 256>>>((const float*)p_h0, W1, (__half*)p_xh1, Nn, DIN, F1);
    }
    attn_logits4<<<(Nn + warpsPB - 1)/warpsPB, T>>>((const __half*)p_xh1, att1_s, att1_d,
                                                    (float*)p_al1s, (float*)p_al1d);

    // join CSR before aggregation
    cudaStreamWaitEvent(0, evJ, 0);

    gat_agg4_fused<<<Nn/4, T>>>((const float4*)p_al1s, (const float4*)p_al1d,
                                (const __half*)p_xh1, bias1, g1, b1, (float*)p_h1);

    {
        dim3 grid(HIDC/GBN, (Nn + GBM - 1)/GBM);
        gemm_tf32<<<grid, 256>>>((const float*)p_h1, W2, (__half*)p_xh2, Nn, F1, HIDC);
    }
    attn_logits1<<<(Nn + warpsPB - 1)/warpsPB, T>>>((const __half*)p_xh2, att2_s, att2_d,
                                                    (float*)p_al2s, (float*)p_al2d);
    gat_agg1_fused<<<(Nn + warpsPB - 1)/warpsPB, T>>>((const float*)p_al2s, (const float*)p_al2d,
                                                      (const __half*)p_xh2, bias2, g2, b2,
                                                      Wo, bo, out);
}